// round 14
// baseline (speedup 1.0000x reference)
#include <cuda_runtime.h>
#include <cuda_fp16.h>
#include <cstddef>
#include <cstdint>

#define BB 8
#define CC 256
#define NN 2304            // 48*48
#define NTILES 18          // NN/128

// ---------------- scratch (static device memory: allowed) ----------------
__device__ __align__(16) float g_y[(size_t)BB*NN*CC];   // y in [b][n][o]
__device__ float g_mean[CC];
__device__ float g_rstd[CC];
__device__ float g_p1[NTILES][CC];   // BN partials (W2 epilogue)
__device__ float g_p2[NTILES][CC];
__device__ __align__(16) float g_mt[(size_t)BB*NN*NTILES];    // per-row tile max
__device__ __align__(16) float g_st[(size_t)BB*NN*NTILES];    // per-row tile expsum
__device__ __align__(16) float g_scale[(size_t)BB*NN*NTILES]; // final row-tile scales

// fp16 operands (hi/lo split where needed)
__device__ __align__(16) __half g_xth[(size_t)BB*NN*CC],  g_xtl[(size_t)BB*NN*CC];   // xT [b][n][c]
__device__ __align__(16) __half g_kqth[(size_t)BB*NN*512], g_kqtl[(size_t)BB*NN*512]; // [b][n][k|q]
__device__ __align__(16) __half g_v  [(size_t)BB*CC*NN];                              // v single fp16
__device__ __align__(16) __half g_at [(size_t)BB*NN*CC];                              // attnT single fp16
__device__ __align__(16) __half g_p  [(size_t)BB*NN*NN];                              // e then P (in place)
__device__ __align__(16) __half g_wkqh[2*CC*CC], g_wkql[2*CC*CC];  // [Wk;Wq]
__device__ __align__(16) __half g_wvh[CC*CC], g_wvl[CC*CC];
__device__ __align__(16) __half g_w2h[CC*CC], g_w2l[CC*CC];

// ---------------- helpers ----------------
__device__ __forceinline__ void split_h(float f, __half& h, __half& l) {
    h = __float2half_rn(f);
    l = __float2half_rn(f - __half2float(h));
}

__device__ __forceinline__ void ldsm4(uint32_t& r0, uint32_t& r1, uint32_t& r2, uint32_t& r3,
                                      const void* p) {
    uint32_t a = (uint32_t)__cvta_generic_to_shared(p);
    asm volatile("ldmatrix.sync.aligned.m8n8.x4.shared.b16 {%0,%1,%2,%3}, [%4];\n"
                 : "=r"(r0), "=r"(r1), "=r"(r2), "=r"(r3) : "r"(a));
}

__device__ __forceinline__ void mma16816(float* c, const uint32_t* a, const uint32_t* b) {
    asm volatile("mma.sync.aligned.m16n8k16.row.col.f32.f16.f16.f32 "
                 "{%0,%1,%2,%3}, {%4,%5,%6,%7}, {%8,%9}, {%0,%1,%2,%3};\n"
                 : "+f"(c[0]), "+f"(c[1]), "+f"(c[2]), "+f"(c[3])
                 : "r"(a[0]), "r"(a[1]), "r"(a[2]), "r"(a[3]), "r"(b[0]), "r"(b[1]));
}

__device__ __forceinline__ void cpasync16(void* s, const void* g) {
    uint32_t a = (uint32_t)__cvta_generic_to_shared(s);
    asm volatile("cp.async.cg.shared.global [%0], [%1], 16;\n" :: "r"(a), "l"(g));
}
__device__ __forceinline__ void cp_commit() { asm volatile("cp.async.commit_group;\n" ::); }

// =========================================================================
// split-fp16 tensor-core GEMM: D[b][M0+r][N0+c] = sum_k A[r][k]*B[c][k]
// TERMS bitmask: 1 = Ah*Bh (always), 2 = Ah*Bl, 4 = Al*Bh.
// Block tile 128x128, 256 threads (2x4 warps, warp tile 64x32), K-chunk 32,
// NSTAGES-deep cp.async pipeline, 2 CTAs/SM.
// STATS: (with Df) fused BN partial sums via atomics.
// SMAX : softmax-prep epilogue — writes e=exp(s-m_tile) fp16 to Dh and
//        per-(row,tile) max/expsum to g_mt/g_st. (tile = blockIdx.x)
// =========================================================================
template<int TERMS, int NSTAGES, bool STATS, bool SMAX>
__global__ __launch_bounds__(256, 2) void mma_split_gemm(
    const __half* __restrict__ Ah, const __half* __restrict__ Al,
    size_t aBatch, int aStride,
    const __half* __restrict__ Bh, const __half* __restrict__ Bl,
    size_t bBatch, int bStride,
    float* __restrict__ Df,
    __half* __restrict__ Dh, __half* __restrict__ Dl,
    const float* __restrict__ bias,
    size_t dBatch, int dStride, int Ktot)
{
    constexpr int ABUFS = (TERMS & 4) ? 2 : 1;
    constexpr int BBUFS = (TERMS & 2) ? 2 : 1;
    constexpr int ASZ = 128 * 40;
    constexpr int BSZ = 128 * 40;
    constexpr int STG = ABUFS * ASZ + BBUFS * BSZ;

    extern __shared__ __align__(16) __half smem[];
#define AHH(s)  (smem + (s)*STG)
#define ALL_(s) (smem + (s)*STG + ASZ)
#define BHH(s)  (smem + (s)*STG + ABUFS*ASZ)
#define BLL(s)  (smem + (s)*STG + ABUFS*ASZ + BSZ)

    const int b  = blockIdx.z;
    const int M0 = blockIdx.y * 128;
    const int N0 = blockIdx.x * 128;
    const int tid  = threadIdx.x;
    const int lane = tid & 31;
    const int warp = tid >> 5;
    const int wm = warp >> 2;     // 0..1
    const int wn = warp & 3;      // 0..3

    const __half* Abh = Ah + (size_t)b*aBatch + (size_t)M0*aStride;
    const __half* Abl = (TERMS & 4) ? Al + (size_t)b*aBatch + (size_t)M0*aStride : nullptr;
    const __half* Bbh = Bh + (size_t)b*bBatch + (size_t)N0*bStride;
    const __half* Bbl = (TERMS & 2) ? Bl + (size_t)b*bBatch + (size_t)N0*bStride : nullptr;

    float acc[4][4][4];
#pragma unroll
    for (int i = 0; i < 4; i++)
#pragma unroll
        for (int j = 0; j < 4; j++)
#pragma unroll
            for (int r = 0; r < 4; r++) acc[i][j][r] = 0.f;

    const int T = Ktot >> 5;   // K chunks of 32

    auto load_stage = [&](int s, int k0) {
#pragma unroll
        for (int it = 0; it < 2; it++) {
            int e = tid + it*256;
            int row = e >> 2, seg = (e & 3) * 8;
            cpasync16(AHH(s)+row*40+seg, Abh + (size_t)row*aStride + k0 + seg);
            if (TERMS & 4) cpasync16(ALL_(s)+row*40+seg, Abl + (size_t)row*aStride + k0 + seg);
            cpasync16(BHH(s)+row*40+seg, Bbh + (size_t)row*bStride + k0 + seg);
            if (TERMS & 2) cpasync16(BLL(s)+row*40+seg, Bbl + (size_t)row*bStride + k0 + seg);
        }
    };

#pragma unroll
    for (int s = 0; s < NSTAGES-1; s++) { load_stage(s, s*32); cp_commit(); }

    int cur = 0, fill = NSTAGES - 1;
    for (int t = 0; t < T; t++) {
        asm volatile("cp.async.wait_group %0;\n" :: "n"(NSTAGES-2));
        __syncthreads();

        if (t + NSTAGES - 1 < T) load_stage(fill, (t + NSTAGES - 1) * 32);
        cp_commit();

#pragma unroll
        for (int kk = 0; kk < 32; kk += 16) {
            uint32_t Bfh[4][2], Bfl[4][2];
#pragma unroll
            for (int p = 0; p < 2; p++) {
                int r = wn*32 + p*16 + ((lane >> 4) << 3) + (lane & 7);
                int c = kk + (((lane >> 3) & 1) << 3);
                uint32_t r0, r1, r2, r3;
                ldsm4(r0, r1, r2, r3, BHH(cur)+r*40+c);
                Bfh[2*p][0] = r0; Bfh[2*p][1] = r1;
                Bfh[2*p+1][0] = r2; Bfh[2*p+1][1] = r3;
                if (TERMS & 2) {
                    ldsm4(r0, r1, r2, r3, BLL(cur)+r*40+c);
                    Bfl[2*p][0] = r0; Bfl[2*p][1] = r1;
                    Bfl[2*p+1][0] = r2; Bfl[2*p+1][1] = r3;
                }
            }
#pragma unroll
            for (int mi = 0; mi < 4; mi++) {
                int r = wm*64 + mi*16 + (lane & 15);
                int c = kk + ((lane >> 4) << 3);
                uint32_t Ahf[4], Alf[4];
                ldsm4(Ahf[0], Ahf[1], Ahf[2], Ahf[3], AHH(cur)+r*40+c);
                if (TERMS & 4) ldsm4(Alf[0], Alf[1], Alf[2], Alf[3], ALL_(cur)+r*40+c);
#pragma unroll
                for (int ni = 0; ni < 4; ni++) mma16816(acc[mi][ni], Ahf, Bfh[ni]);
                if (TERMS & 2) {
#pragma unroll
                    for (int ni = 0; ni < 4; ni++) mma16816(acc[mi][ni], Ahf, Bfl[ni]);
                }
                if (TERMS & 4) {
#pragma unroll
                    for (int ni = 0; ni < 4; ni++) mma16816(acc[mi][ni], Alf, Bfh[ni]);
                }
            }
        }
        cur = (cur + 1 == NSTAGES) ? 0 : cur + 1;
        fill = (fill + 1 == NSTAGES) ? 0 : fill + 1;
    }

    const int g = lane >> 2, tg2 = (lane & 3) * 2;

    if (SMAX) {
        // ------- softmax-prep epilogue -------
        float* maxarr = (float*)smem;          // [128][4]
        float* sumarr = (float*)smem + 512;    // [128][4]
        __syncthreads();   // stage buffers retired; smem reusable

        // per-(mi,half) local row max over this thread's 8 cols, reduce in quad
#pragma unroll
        for (int mi = 0; mi < 4; mi++) {
            float m0 = -1e30f, m1 = -1e30f;
#pragma unroll
            for (int ni = 0; ni < 4; ni++) {
                m0 = fmaxf(m0, fmaxf(acc[mi][ni][0], acc[mi][ni][1]));
                m1 = fmaxf(m1, fmaxf(acc[mi][ni][2], acc[mi][ni][3]));
            }
            m0 = fmaxf(m0, __shfl_xor_sync(0xffffffffu, m0, 1));
            m0 = fmaxf(m0, __shfl_xor_sync(0xffffffffu, m0, 2));
            m1 = fmaxf(m1, __shfl_xor_sync(0xffffffffu, m1, 1));
            m1 = fmaxf(m1, __shfl_xor_sync(0xffffffffu, m1, 2));
            if ((lane & 3) == 0) {
                int r0 = wm*64 + mi*16 + g;
                maxarr[r0*4 + wn]     = m0;
                maxarr[(r0+8)*4 + wn] = m1;
            }
        }
        __syncthreads();

        // final tile max per row, exp, fp16 write, tile sum
        __half* Dbh = Dh + (size_t)b*dBatch;
#pragma unroll
        for (int mi = 0; mi < 4; mi++) {
            int r0 = wm*64 + mi*16 + g;
            float mt0 = fmaxf(fmaxf(maxarr[r0*4+0], maxarr[r0*4+1]),
                              fmaxf(maxarr[r0*4+2], maxarr[r0*4+3]));
            float mt1 = fmaxf(fmaxf(maxarr[(r0+8)*4+0], maxarr[(r0+8)*4+1]),
                              fmaxf(maxarr[(r0+8)*4+2], maxarr[(r0+8)*4+3]));
            float s0 = 0.f, s1 = 0.f;
#pragma unroll
            for (int ni = 0; ni < 4; ni++) {
                int row = M0 + r0;
                int col = N0 + wn*32 + ni*8 + tg2;
                float e0 = __expf(acc[mi][ni][0] - mt0);
                float e1 = __expf(acc[mi][ni][1] - mt0);
                float e2 = __expf(acc[mi][ni][2] - mt1);
                float e3 = __expf(acc[mi][ni][3] - mt1);
                s0 += e0 + e1; s1 += e2 + e3;
                *(__half2*)&Dbh[(size_t)row*dStride + col]     = __floats2half2_rn(e0, e1);
                *(__half2*)&Dbh[(size_t)(row+8)*dStride + col] = __floats2half2_rn(e2, e3);
            }
            s0 += __shfl_xor_sync(0xffffffffu, s0, 1);
            s0 += __shfl_xor_sync(0xffffffffu, s0, 2);
            s1 += __shfl_xor_sync(0xffffffffu, s1, 1);
            s1 += __shfl_xor_sync(0xffffffffu, s1, 2);
            if ((lane & 3) == 0) {
                sumarr[r0*4 + wn]     = s0;
                sumarr[(r0+8)*4 + wn] = s1;
            }
        }
        __syncthreads();

        if (wn == 0 && (lane & 3) == 0) {
            const int tile = blockIdx.x;
#pragma unroll
            for (int mi = 0; mi < 4; mi++) {
                int r0 = wm*64 + mi*16 + g;
#pragma unroll
                for (int h = 0; h < 2; h++) {
                    int r = r0 + h*8;
                    float mm = fmaxf(fmaxf(maxarr[r*4+0], maxarr[r*4+1]),
                                     fmaxf(maxarr[r*4+2], maxarr[r*4+3]));
                    float tt = sumarr[r*4+0]+sumarr[r*4+1]+sumarr[r*4+2]+sumarr[r*4+3];
                    size_t idx = ((size_t)b*NN + M0 + r)*NTILES + tile;
                    g_mt[idx] = mm;
                    g_st[idx] = tt;
                }
            }
        }
    } else if (Df) {
        float* Db = Df + (size_t)b*dBatch;
        float s1[4][2], s2[4][2];
        if (STATS) {
#pragma unroll
            for (int ni = 0; ni < 4; ni++) { s1[ni][0]=s1[ni][1]=s2[ni][0]=s2[ni][1]=0.f; }
        }
#pragma unroll
        for (int mi = 0; mi < 4; mi++)
#pragma unroll
            for (int ni = 0; ni < 4; ni++) {
                int row = M0 + wm*64 + mi*16 + g;
                int col = N0 + wn*32 + ni*8 + tg2;
                float b0 = bias ? bias[col] : 0.f;
                float b1 = bias ? bias[col+1] : 0.f;
                float v0 = acc[mi][ni][0]+b0, v1 = acc[mi][ni][1]+b1;
                float v2 = acc[mi][ni][2]+b0, v3 = acc[mi][ni][3]+b1;
                *(float2*)&Db[(size_t)row*dStride + col]     = make_float2(v0, v1);
                *(float2*)&Db[(size_t)(row+8)*dStride + col] = make_float2(v2, v3);
                if (STATS) {
                    s1[ni][0] += v0 + v2;  s1[ni][1] += v1 + v3;
                    s2[ni][0] += v0*v0 + v2*v2;  s2[ni][1] += v1*v1 + v3*v3;
                }
            }
        if (STATS) {
#pragma unroll
            for (int ni = 0; ni < 4; ni++)
#pragma unroll
                for (int cix = 0; cix < 2; cix++) {
#pragma unroll
                    for (int off = 16; off >= 4; off >>= 1) {
                        s1[ni][cix] += __shfl_xor_sync(0xffffffffu, s1[ni][cix], off);
                        s2[ni][cix] += __shfl_xor_sync(0xffffffffu, s2[ni][cix], off);
                    }
                }
            if (lane < 4) {
                const int slab = blockIdx.y;
#pragma unroll
                for (int ni = 0; ni < 4; ni++) {
                    int col = N0 + wn*32 + ni*8 + lane*2;
                    atomicAdd(&g_p1[slab][col],   s1[ni][0]);
                    atomicAdd(&g_p2[slab][col],   s2[ni][0]);
                    atomicAdd(&g_p1[slab][col+1], s1[ni][1]);
                    atomicAdd(&g_p2[slab][col+1], s2[ni][1]);
                }
            }
        }
    } else if (Dl) {
        __half* Dbh = Dh + (size_t)b*dBatch;
        __half* Dbl = Dl + (size_t)b*dBatch;
#pragma unroll
        for (int mi = 0; mi < 4; mi++)
#pragma unroll
            for (int ni = 0; ni < 4; ni++) {
                int row = M0 + wm*64 + mi*16 + g;
                int col = N0 + wn*32 + ni*8 + tg2;
                __half h0,l0,h1,l1;
                split_h(acc[mi][ni][0], h0, l0);
                split_h(acc[mi][ni][1], h1, l1);
                *(__half2*)&Dbh[(size_t)row*dStride + col] = __halves2half2(h0, h1);
                *(__half2*)&Dbl[(size_t)row*dStride + col] = __halves2half2(l0, l1);
                split_h(acc[mi][ni][2], h0, l0);
                split_h(acc[mi][ni][3], h1, l1);
                *(__half2*)&Dbh[(size_t)(row+8)*dStride + col] = __halves2half2(h0, h1);
                *(__half2*)&Dbl[(size_t)(row+8)*dStride + col] = __halves2half2(l0, l1);
            }
    } else {
        __half* Dbh = Dh + (size_t)b*dBatch;
#pragma unroll
        for (int mi = 0; mi < 4; mi++)
#pragma unroll
            for (int ni = 0; ni < 4; ni++) {
                int row = M0 + wm*64 + mi*16 + g;
                int col = N0 + wn*32 + ni*8 + tg2;
                *(__half2*)&Dbh[(size_t)row*dStride + col] =
                    __halves2half2(__float2half_rn(acc[mi][ni][0]), __float2half_rn(acc[mi][ni][1]));
                *(__half2*)&Dbh[(size_t)(row+8)*dStride + col] =
                    __halves2half2(__float2half_rn(acc[mi][ni][2]), __float2half_rn(acc[mi][ni][3]));
            }
    }
#undef AHH
#undef ALL_
#undef BHH
#undef BLL
}

// =========================================================================
// merged weight split + stat-buffer zeroing
// =========================================================================
__global__ __launch_bounds__(256) void wsplit_all(
    const float* __restrict__ Wk, const float* __restrict__ Wq,
    const float* __restrict__ Wv, const float* __restrict__ W2)
{
    const int sel = blockIdx.y;
    const float* W = sel == 0 ? Wk : sel == 1 ? Wq : sel == 2 ? Wv : W2;
    __half* h = sel == 0 ? g_wkqh : sel == 1 ? (g_wkqh + CC*CC)
              : sel == 2 ? g_wvh : g_w2h;
    __half* l = sel == 0 ? g_wkql : sel == 1 ? (g_wkql + CC*CC)
              : sel == 2 ? g_wvl : g_w2l;
    int i = blockIdx.x * 256 + threadIdx.x;
    split_h(W[i], h[i], l[i]);
    int z = (blockIdx.y * gridDim.x + blockIdx.x) * 256 + threadIdx.x;
    if (z < NTILES*CC) { (&g_p1[0][0])[z] = 0.f; (&g_p2[0][0])[z] = 0.f; }
}

// =========================================================================
// x transpose + split: x [b][c][n] fp32 -> xT hi/lo [b][n][c]
// =========================================================================
__global__ __launch_bounds__(256) void xsplit_kernel(const float* __restrict__ x)
{
    __shared__ float Tm[32][33];
    const int b = blockIdx.z;
    const float* src = x + (size_t)b*CC*NN;
    __half* dh = g_xth + (size_t)b*NN*CC;
    __half* dl = g_xtl + (size_t)b*NN*CC;
    const int n0 = blockIdx.x * 32, c0 = blockIdx.y * 32;
    const int tx = threadIdx.x & 31, ty = threadIdx.x >> 5;

#pragma unroll
    for (int j = 0; j < 4; j++)
        Tm[ty + j*8][tx] = src[(size_t)(c0 + ty + j*8)*NN + n0 + tx];
    __syncthreads();
#pragma unroll
    for (int j = 0; j < 4; j++) {
        float v = Tm[tx][ty + j*8];
        int n = n0 + ty + j*8;
        __half h, l;
        split_h(v, h, l);
        dh[(size_t)n*CC + c0 + tx] = h;
        dl[(size_t)n*CC + c0 + tx] = l;
    }
}

// =========================================================================
// softmax finalize: per row combine tile (max, expsum) -> scale per tile
// =========================================================================
__global__ __launch_bounds__(256) void smax_fin()
{
    int row = blockIdx.x * 256 + threadIdx.x;     // 0 .. BB*NN-1
    const float* mt = g_mt + (size_t)row*NTILES;
    const float* st = g_st + (size_t)row*NTILES;
    float* sc = g_scale + (size_t)row*NTILES;
    float m = mt[0];
#pragma unroll
    for (int i = 1; i < NTILES; i++) m = fmaxf(m, mt[i]);
    float e[NTILES];
    float tot = 0.f;
#pragma unroll
    for (int i = 0; i < NTILES; i++) { e[i] = __expf(mt[i] - m); tot += st[i]*e[i]; }
    float inv = 1.0f / tot;
#pragma unroll
    for (int i = 0; i < NTILES; i++) sc[i] = e[i]*inv;
}

// =========================================================================
// rescale: P = e * scale[row][tile], in place on g_p
// grid (NN, BB), block 288; thread handles 8 contiguous halfs
// =========================================================================
__global__ __launch_bounds__(288) void rescale_kernel()
{
    const int b = blockIdx.y, n = blockIdx.x;
    const int tid = threadIdx.x;
    __half* row = g_p + ((size_t)b*NN + n) * NN;
    float s = g_scale[((size_t)b*NN + n)*NTILES + (tid >> 4)];
    uint4 u = *(uint4*)&row[tid*8];
    __half2* hp = (__half2*)&u;
#pragma unroll
    for (int i = 0; i < 4; i++) {
        float2 f = __half22float2(hp[i]);
        hp[i] = __floats2half2_rn(f.x*s, f.y*s);
    }
    *(uint4*)&row[tid*8] = u;
}

// =========================================================================
// BN finalize from W2-epilogue partials
// =========================================================================
__global__ __launch_bounds__(256) void bnstats_fin()
{
    const int o = threadIdx.x;
    float S1 = 0.f, S2 = 0.f;
#pragma unroll
    for (int s = 0; s < NTILES; s++) { S1 += g_p1[s][o]; S2 += g_p2[s][o]; }
    const float invM = 1.0f / (float)(BB*NN);
    float mean = S1 * invM;
    float var  = S2 * invM - mean*mean;
    g_mean[o] = mean;
    g_rstd[o] = rsqrtf(var + 1e-5f);
}

// =========================================================================
// normalize + affine + transpose: y [b][n][o] -> out [b][o][n]
// =========================================================================
__global__ __launch_bounds__(256) void bnorm_kernel(
    const float* __restrict__ gamma, const float* __restrict__ beta,
    float* __restrict__ out)
{
    __shared__ float Tm[32][33];
    const int b = blockIdx.z;
    const int n0 = blockIdx.x * 32, o0 = blockIdx.y * 32;
    const int tx = threadIdx.x & 31, ty = threadIdx.x >> 5;
    const float* yb = g_y + (size_t)b*NN*CC;
#pragma unroll
    for (int j = 0; j < 4; j++)
        Tm[ty + j*8][tx] = yb[(size_t)(n0 + ty + j*8)*CC + o0 + tx];
    __syncthreads();
#pragma unroll
    for (int j = 0; j < 4; j++) {
        int o = o0 + ty + j*8;
        float sc = g_rstd[o] * gamma[o];
        float mb = g_mean[o];
        out[((size_t)b*CC + o)*NN + n0 + tx] = (Tm[tx][ty + j*8] - mb) * sc + beta[o];
    }
}

// =========================================================================
extern "C" void kernel_launch(void* const* d_in, const int* in_sizes, int n_in,
                              void* d_out, int out_size)
{
    (void)in_sizes; (void)n_in; (void)out_size;
    const float* x     = (const float*)d_in[0];
    const float* Wk    = (const float*)d_in[1];
    const float* Wq    = (const float*)d_in[2];
    const float* Wv    = (const float*)d_in[3];
    const float* W2    = (const float*)d_in[4];
    const float* b2    = (const float*)d_in[5];
    const float* gamma = (const float*)d_in[6];
    const float* beta  = (const float*)d_in[7];
    float* out = (float*)d_out;

    float *py;
    __half *pxth,*pxtl,*pkqth,*pkqtl,*pv,*pat,*pp;
    __half *pwkqh,*pwkql,*pwvh,*pwvl,*pw2h,*pw2l;
    cudaGetSymbolAddress((void**)&py,    g_y);
    cudaGetSymbolAddress((void**)&pxth,  g_xth);  cudaGetSymbolAddress((void**)&pxtl,  g_xtl);
    cudaGetSymbolAddress((void**)&pkqth, g_kqth); cudaGetSymbolAddress((void**)&pkqtl, g_kqtl);
    cudaGetSymbolAddress((void**)&pv,    g_v);
    cudaGetSymbolAddress((void**)&pat,   g_at);   cudaGetSymbolAddress((void**)&pp,    g_p);
    cudaGetSymbolAddress((void**)&pwkqh, g_wkqh); cudaGetSymbolAddress((void**)&pwkql, g_wkql);
    cudaGetSymbolAddress((void**)&pwvh,  g_wvh);  cudaGetSymbolAddress((void**)&pwvl,  g_wvl);
    cudaGetSymbolAddress((void**)&pw2h,  g_w2h);  cudaGetSymbolAddress((void**)&pw2l,  g_w2l);

    const int SM7 = 2 * (4*128*40) * 2;  // 81920   (TERMS=7, 2 stages)
    const int SM5 = 3 * (3*128*40) * 2;  // 92160   (TERMS=5, 3 stages)
    const int SM3 = 3 * (3*128*40) * 2;  // 92160   (TERMS=3, 3 stages)
    const int SM1 = 4 * (2*128*40) * 2;  // 81920   (TERMS=1, 4 stages)
    cudaFuncSetAttribute(mma_split_gemm<7,2,false,false>, cudaFuncAttributeMaxDynamicSharedMemorySize, SM7);
    cudaFuncSetAttribute(mma_split_gemm<5,3,false,false>, cudaFuncAttributeMaxDynamicSharedMemorySize, SM5);
    cudaFuncSetAttribute(mma_split_gemm<7,2,false,true>,  cudaFuncAttributeMaxDynamicSharedMemorySize, SM7);
    cudaFuncSetAttribute(mma_split_gemm<3,3,true,false>,  cudaFuncAttributeMaxDynamicSharedMemorySize, SM3);
    cudaFuncSetAttribute(mma_split_gemm<1,4,false,false>, cudaFuncAttributeMaxDynamicSharedMemorySize, SM1);

    dim3 blk(256);

    wsplit_all<<<dim3(CC*CC/256, 4), blk>>>(Wk, Wq, Wv, W2);

    xsplit_kernel<<<dim3(NN/32, CC/32, BB), blk>>>(x);

    // kqT[b][n][o] = sum_c xT[n][c] * Wkq[o][c]  (3 terms, split out)
    mma_split_gemm<7,2,false,false><<<dim3(512/128, NN/128, BB), blk, SM7>>>(
        pxth, pxtl, (size_t)NN*CC, CC,  pwkqh, pwkql, 0, CC,
        nullptr, pkqth, pkqtl, nullptr, (size_t)NN*512, 512, CC);

    // v[b][c][m] = sum_c' Wv[c][c'] * xT[m][c']  (2 terms; single fp16 out)
    mma_split_gemm<5,3,false,false><<<dim3(NN/128, CC/128, BB), blk, SM5>>>(
        pwvh, pwvl, 0, CC,  pxth, pxtl, (size_t)NN*CC, CC,
        nullptr, pv, nullptr, nullptr, (size_t)CC*NN, NN, CC);

    // scores + softmax-prep: e[b][n][m] = exp(s - m_tile) fp16 into g_p,
    // per-(row, tile) stats into g_mt/g_st
    mma_split_gemm<7,2,false,true><<<dim3(NN/128, NN/128, BB), blk, SM7>>>(
        pkqth, pkqtl, (size_t)NN*512, 512,
        pkqth + CC, pkqtl + CC, (size_t)NN*512, 512,
        nullptr, pp, nullptr, nullptr, (size_t)NN*NN, NN, CC);

    smax_fin<<<BB*NN/256, blk>>>();

    rescale_kernel<<<dim3(NN, BB), 288>>>();

    // attnT[b][n][c] = sum_m P[n][m]*v[c][m]  (1 term)
    mma_split_gemm<1,4,false,false><<<dim3(CC/128, NN/128, BB), blk, SM1>>>(
        pp, nullptr, (size_t)NN*NN, NN,  pv, nullptr, (size_t)CC*NN, NN,
        nullptr, pat, nullptr, nullptr, (size_t)NN*CC, CC, NN);

    // y[b][n][o] = sum_c attnT[n][c]*W2[o][c] + b2[o]  (2 terms; fp32 + BN stats)
    mma_split_gemm<3,3,true,false><<<dim3(CC/128, NN/128, BB), blk, SM3>>>(
        pat, nullptr, (size_t)NN*CC, CC,  pw2h, pw2l, 0, CC,
        py, nullptr, nullptr, b2, (size_t)NN*CC, CC, CC);

    bnstats_fin<<<1, CC>>>();

    bnorm_kernel<<<dim3(NN/32, CC/32, BB), blk>>>(gamma, beta, out);
}

// round 15
// speedup vs baseline: 1.0267x; 1.0267x over previous
#include <cuda_runtime.h>
#include <cuda_fp16.h>
#include <cstddef>
#include <cstdint>

#define BB 8
#define CC 256
#define NN 2304            // 48*48
#define NTILES 18          // NN/128

// ---------------- scratch (static device memory: allowed) ----------------
__device__ __align__(16) float g_y[(size_t)BB*NN*CC];   // y in [b][n][o]
__device__ float g_mean[CC];
__device__ float g_rstd[CC];
__device__ float g_p1[NTILES][CC];   // BN partials (W2 epilogue)
__device__ float g_p2[NTILES][CC];
__device__ __align__(16) float g_mt[(size_t)BB*NN*NTILES];    // per-row tile max
__device__ __align__(16) float g_st[(size_t)BB*NN*NTILES];    // per-row tile expsum
__device__ __align__(16) float g_scale[(size_t)BB*NN*NTILES]; // final row-tile scales

// fp16 operands (hi/lo split where needed)
__device__ __align__(16) __half g_xth[(size_t)BB*NN*CC],  g_xtl[(size_t)BB*NN*CC];   // xT [b][n][c]
__device__ __align__(16) __half g_kqth[(size_t)BB*NN*512], g_kqtl[(size_t)BB*NN*512]; // [b][n][k|q]
__device__ __align__(16) __half g_v  [(size_t)BB*CC*NN];                              // v single fp16
__device__ __align__(16) __half g_at [(size_t)BB*NN*CC];                              // attnT single fp16
__device__ __align__(16) __half g_p  [(size_t)BB*NN*NN];                              // e (unscaled exp)
__device__ __align__(16) __half g_wkqh[2*CC*CC], g_wkql[2*CC*CC];  // [Wk;Wq]
__device__ __align__(16) __half g_wvh[CC*CC], g_wvl[CC*CC];
__device__ __align__(16) __half g_w2h[CC*CC], g_w2l[CC*CC];

// ---------------- helpers ----------------
__device__ __forceinline__ void split_h(float f, __half& h, __half& l) {
    h = __float2half_rn(f);
    l = __float2half_rn(f - __half2float(h));
}

__device__ __forceinline__ void ldsm4(uint32_t& r0, uint32_t& r1, uint32_t& r2, uint32_t& r3,
                                      const void* p) {
    uint32_t a = (uint32_t)__cvta_generic_to_shared(p);
    asm volatile("ldmatrix.sync.aligned.m8n8.x4.shared.b16 {%0,%1,%2,%3}, [%4];\n"
                 : "=r"(r0), "=r"(r1), "=r"(r2), "=r"(r3) : "r"(a));
}

__device__ __forceinline__ void mma16816(float* c, const uint32_t* a, const uint32_t* b) {
    asm volatile("mma.sync.aligned.m16n8k16.row.col.f32.f16.f16.f32 "
                 "{%0,%1,%2,%3}, {%4,%5,%6,%7}, {%8,%9}, {%0,%1,%2,%3};\n"
                 : "+f"(c[0]), "+f"(c[1]), "+f"(c[2]), "+f"(c[3])
                 : "r"(a[0]), "r"(a[1]), "r"(a[2]), "r"(a[3]), "r"(b[0]), "r"(b[1]));
}

__device__ __forceinline__ void cpasync16(void* s, const void* g) {
    uint32_t a = (uint32_t)__cvta_generic_to_shared(s);
    asm volatile("cp.async.cg.shared.global [%0], [%1], 16;\n" :: "r"(a), "l"(g));
}
__device__ __forceinline__ void cp_commit() { asm volatile("cp.async.commit_group;\n" ::); }

// =========================================================================
// split-fp16 tensor-core GEMM: D[b][M0+r][N0+c] = sum_k A[r][k]*B[c][k]
// TERMS bitmask: 1 = Ah*Bh (always), 2 = Ah*Bl, 4 = Al*Bh.
// Block tile 128x128, 256 threads (2x4 warps, warp tile 64x32), K-chunk 32,
// NSTAGES-deep cp.async pipeline, 2 CTAs/SM.
// STATS  : (with Df) fused BN partial sums via atomics.
// SMAX   : softmax-prep epilogue (writes e=exp(s-m_tile) fp16 + tile stats).
// PVSCALE: multiply A fragments by g_scale[row][k0/128] (softmax rescale
//          folded into the PV mainloop; valid for TERMS=1).
// =========================================================================
template<int TERMS, int NSTAGES, bool STATS, bool SMAX, bool PVSCALE>
__global__ __launch_bounds__(256, 2) void mma_split_gemm(
    const __half* __restrict__ Ah, const __half* __restrict__ Al,
    size_t aBatch, int aStride,
    const __half* __restrict__ Bh, const __half* __restrict__ Bl,
    size_t bBatch, int bStride,
    float* __restrict__ Df,
    __half* __restrict__ Dh, __half* __restrict__ Dl,
    const float* __restrict__ bias,
    size_t dBatch, int dStride, int Ktot)
{
    constexpr int ABUFS = (TERMS & 4) ? 2 : 1;
    constexpr int BBUFS = (TERMS & 2) ? 2 : 1;
    constexpr int ASZ = 128 * 40;
    constexpr int BSZ = 128 * 40;
    constexpr int STG = ABUFS * ASZ + BBUFS * BSZ;

    extern __shared__ __align__(16) __half smem[];
#define AHH(s)  (smem + (s)*STG)
#define ALL_(s) (smem + (s)*STG + ASZ)
#define BHH(s)  (smem + (s)*STG + ABUFS*ASZ)
#define BLL(s)  (smem + (s)*STG + ABUFS*ASZ + BSZ)

    const int b  = blockIdx.z;
    const int M0 = blockIdx.y * 128;
    const int N0 = blockIdx.x * 128;
    const int tid  = threadIdx.x;
    const int lane = tid & 31;
    const int warp = tid >> 5;
    const int wm = warp >> 2;     // 0..1
    const int wn = warp & 3;      // 0..3

    const __half* Abh = Ah + (size_t)b*aBatch + (size_t)M0*aStride;
    const __half* Abl = (TERMS & 4) ? Al + (size_t)b*aBatch + (size_t)M0*aStride : nullptr;
    const __half* Bbh = Bh + (size_t)b*bBatch + (size_t)N0*bStride;
    const __half* Bbl = (TERMS & 2) ? Bl + (size_t)b*bBatch + (size_t)N0*bStride : nullptr;

    float acc[4][4][4];
#pragma unroll
    for (int i = 0; i < 4; i++)
#pragma unroll
        for (int j = 0; j < 4; j++)
#pragma unroll
            for (int r = 0; r < 4; r++) acc[i][j][r] = 0.f;

    const int T = Ktot >> 5;   // K chunks of 32

    auto load_stage = [&](int s, int k0) {
#pragma unroll
        for (int it = 0; it < 2; it++) {
            int e = tid + it*256;
            int row = e >> 2, seg = (e & 3) * 8;
            cpasync16(AHH(s)+row*40+seg, Abh + (size_t)row*aStride + k0 + seg);
            if (TERMS & 4) cpasync16(ALL_(s)+row*40+seg, Abl + (size_t)row*aStride + k0 + seg);
            cpasync16(BHH(s)+row*40+seg, Bbh + (size_t)row*bStride + k0 + seg);
            if (TERMS & 2) cpasync16(BLL(s)+row*40+seg, Bbl + (size_t)row*bStride + k0 + seg);
        }
    };

#pragma unroll
    for (int s = 0; s < NSTAGES-1; s++) { load_stage(s, s*32); cp_commit(); }

    int cur = 0, fill = NSTAGES - 1;
    for (int t = 0; t < T; t++) {
        asm volatile("cp.async.wait_group %0;\n" :: "n"(NSTAGES-2));
        __syncthreads();

        if (t + NSTAGES - 1 < T) load_stage(fill, (t + NSTAGES - 1) * 32);
        cp_commit();

#pragma unroll
        for (int kk = 0; kk < 32; kk += 16) {
            uint32_t Bfh[4][2], Bfl[4][2];
#pragma unroll
            for (int p = 0; p < 2; p++) {
                int r = wn*32 + p*16 + ((lane >> 4) << 3) + (lane & 7);
                int c = kk + (((lane >> 3) & 1) << 3);
                uint32_t r0, r1, r2, r3;
                ldsm4(r0, r1, r2, r3, BHH(cur)+r*40+c);
                Bfh[2*p][0] = r0; Bfh[2*p][1] = r1;
                Bfh[2*p+1][0] = r2; Bfh[2*p+1][1] = r3;
                if (TERMS & 2) {
                    ldsm4(r0, r1, r2, r3, BLL(cur)+r*40+c);
                    Bfl[2*p][0] = r0; Bfl[2*p][1] = r1;
                    Bfl[2*p+1][0] = r2; Bfl[2*p+1][1] = r3;
                }
            }
#pragma unroll
            for (int mi = 0; mi < 4; mi++) {
                int r = wm*64 + mi*16 + (lane & 15);
                int c = kk + ((lane >> 4) << 3);
                uint32_t Ahf[4], Alf[4];
                ldsm4(Ahf[0], Ahf[1], Ahf[2], Ahf[3], AHH(cur)+r*40+c);
                if (TERMS & 4) ldsm4(Alf[0], Alf[1], Alf[2], Alf[3], ALL_(cur)+r*40+c);

                if (PVSCALE) {
                    // scale A fragments by softmax row-tile scale.
                    // ldmatrix.x4 frag: regs {0,2} = row g, regs {1,3} = row g+8.
                    const int tile = t >> 2;            // k0/128
                    const int rowa = M0 + wm*64 + mi*16 + (lane >> 2);
                    float s0f = g_scale[((size_t)b*NN + rowa)*NTILES + tile];
                    float s1f = g_scale[((size_t)b*NN + rowa + 8)*NTILES + tile];
                    __half2 hs0 = __half2half2(__float2half_rn(s0f));
                    __half2 hs1 = __half2half2(__float2half_rn(s1f));
                    __half2* ah = (__half2*)Ahf;
                    ah[0] = __hmul2(ah[0], hs0);
                    ah[1] = __hmul2(ah[1], hs1);
                    ah[2] = __hmul2(ah[2], hs0);
                    ah[3] = __hmul2(ah[3], hs1);
                }

#pragma unroll
                for (int ni = 0; ni < 4; ni++) mma16816(acc[mi][ni], Ahf, Bfh[ni]);
                if (TERMS & 2) {
#pragma unroll
                    for (int ni = 0; ni < 4; ni++) mma16816(acc[mi][ni], Ahf, Bfl[ni]);
                }
                if (TERMS & 4) {
#pragma unroll
                    for (int ni = 0; ni < 4; ni++) mma16816(acc[mi][ni], Alf, Bfh[ni]);
                }
            }
        }
        cur = (cur + 1 == NSTAGES) ? 0 : cur + 1;
        fill = (fill + 1 == NSTAGES) ? 0 : fill + 1;
    }

    const int g = lane >> 2, tg2 = (lane & 3) * 2;

    if (SMAX) {
        // ------- softmax-prep epilogue -------
        float* maxarr = (float*)smem;          // [128][4]
        float* sumarr = (float*)smem + 512;    // [128][4]
        __syncthreads();   // stage buffers retired; smem reusable

#pragma unroll
        for (int mi = 0; mi < 4; mi++) {
            float m0 = -1e30f, m1 = -1e30f;
#pragma unroll
            for (int ni = 0; ni < 4; ni++) {
                m0 = fmaxf(m0, fmaxf(acc[mi][ni][0], acc[mi][ni][1]));
                m1 = fmaxf(m1, fmaxf(acc[mi][ni][2], acc[mi][ni][3]));
            }
            m0 = fmaxf(m0, __shfl_xor_sync(0xffffffffu, m0, 1));
            m0 = fmaxf(m0, __shfl_xor_sync(0xffffffffu, m0, 2));
            m1 = fmaxf(m1, __shfl_xor_sync(0xffffffffu, m1, 1));
            m1 = fmaxf(m1, __shfl_xor_sync(0xffffffffu, m1, 2));
            if ((lane & 3) == 0) {
                int r0 = wm*64 + mi*16 + g;
                maxarr[r0*4 + wn]     = m0;
                maxarr[(r0+8)*4 + wn] = m1;
            }
        }
        __syncthreads();

        __half* Dbh = Dh + (size_t)b*dBatch;
#pragma unroll
        for (int mi = 0; mi < 4; mi++) {
            int r0 = wm*64 + mi*16 + g;
            float mt0 = fmaxf(fmaxf(maxarr[r0*4+0], maxarr[r0*4+1]),
                              fmaxf(maxarr[r0*4+2], maxarr[r0*4+3]));
            float mt1 = fmaxf(fmaxf(maxarr[(r0+8)*4+0], maxarr[(r0+8)*4+1]),
                              fmaxf(maxarr[(r0+8)*4+2], maxarr[(r0+8)*4+3]));
            float s0 = 0.f, s1 = 0.f;
#pragma unroll
            for (int ni = 0; ni < 4; ni++) {
                int row = M0 + r0;
                int col = N0 + wn*32 + ni*8 + tg2;
                float e0 = __expf(acc[mi][ni][0] - mt0);
                float e1 = __expf(acc[mi][ni][1] - mt0);
                float e2 = __expf(acc[mi][ni][2] - mt1);
                float e3 = __expf(acc[mi][ni][3] - mt1);
                s0 += e0 + e1; s1 += e2 + e3;
                *(__half2*)&Dbh[(size_t)row*dStride + col]     = __floats2half2_rn(e0, e1);
                *(__half2*)&Dbh[(size_t)(row+8)*dStride + col] = __floats2half2_rn(e2, e3);
            }
            s0 += __shfl_xor_sync(0xffffffffu, s0, 1);
            s0 += __shfl_xor_sync(0xffffffffu, s0, 2);
            s1 += __shfl_xor_sync(0xffffffffu, s1, 1);
            s1 += __shfl_xor_sync(0xffffffffu, s1, 2);
            if ((lane & 3) == 0) {
                sumarr[r0*4 + wn]     = s0;
                sumarr[(r0+8)*4 + wn] = s1;
            }
        }
        __syncthreads();

        if (wn == 0 && (lane & 3) == 0) {
            const int tile = blockIdx.x;
#pragma unroll
            for (int mi = 0; mi < 4; mi++) {
                int r0 = wm*64 + mi*16 + g;
#pragma unroll
                for (int h = 0; h < 2; h++) {
                    int r = r0 + h*8;
                    float mm = fmaxf(fmaxf(maxarr[r*4+0], maxarr[r*4+1]),
                                     fmaxf(maxarr[r*4+2], maxarr[r*4+3]));
                    float tt = sumarr[r*4+0]+sumarr[r*4+1]+sumarr[r*4+2]+sumarr[r*4+3];
                    size_t idx = ((size_t)b*NN + M0 + r)*NTILES + tile;
                    g_mt[idx] = mm;
                    g_st[idx] = tt;
                }
            }
        }
    } else if (Df) {
        float* Db = Df + (size_t)b*dBatch;
        float s1[4][2], s2[4][2];
        if (STATS) {
#pragma unroll
            for (int ni = 0; ni < 4; ni++) { s1[ni][0]=s1[ni][1]=s2[ni][0]=s2[ni][1]=0.f; }
        }
#pragma unroll
        for (int mi = 0; mi < 4; mi++)
#pragma unroll
            for (int ni = 0; ni < 4; ni++) {
                int row = M0 + wm*64 + mi*16 + g;
                int col = N0 + wn*32 + ni*8 + tg2;
                float b0 = bias ? bias[col] : 0.f;
                float b1 = bias ? bias[col+1] : 0.f;
                float v0 = acc[mi][ni][0]+b0, v1 = acc[mi][ni][1]+b1;
                float v2 = acc[mi][ni][2]+b0, v3 = acc[mi][ni][3]+b1;
                *(float2*)&Db[(size_t)row*dStride + col]     = make_float2(v0, v1);
                *(float2*)&Db[(size_t)(row+8)*dStride + col] = make_float2(v2, v3);
                if (STATS) {
                    s1[ni][0] += v0 + v2;  s1[ni][1] += v1 + v3;
                    s2[ni][0] += v0*v0 + v2*v2;  s2[ni][1] += v1*v1 + v3*v3;
                }
            }
        if (STATS) {
#pragma unroll
            for (int ni = 0; ni < 4; ni++)
#pragma unroll
                for (int cix = 0; cix < 2; cix++) {
#pragma unroll
                    for (int off = 16; off >= 4; off >>= 1) {
                        s1[ni][cix] += __shfl_xor_sync(0xffffffffu, s1[ni][cix], off);
                        s2[ni][cix] += __shfl_xor_sync(0xffffffffu, s2[ni][cix], off);
                    }
                }
            if (lane < 4) {
                const int slab = blockIdx.y;
#pragma unroll
                for (int ni = 0; ni < 4; ni++) {
                    int col = N0 + wn*32 + ni*8 + lane*2;
                    atomicAdd(&g_p1[slab][col],   s1[ni][0]);
                    atomicAdd(&g_p2[slab][col],   s2[ni][0]);
                    atomicAdd(&g_p1[slab][col+1], s1[ni][1]);
                    atomicAdd(&g_p2[slab][col+1], s2[ni][1]);
                }
            }
        }
    } else if (Dl) {
        __half* Dbh = Dh + (size_t)b*dBatch;
        __half* Dbl = Dl + (size_t)b*dBatch;
#pragma unroll
        for (int mi = 0; mi < 4; mi++)
#pragma unroll
            for (int ni = 0; ni < 4; ni++) {
                int row = M0 + wm*64 + mi*16 + g;
                int col = N0 + wn*32 + ni*8 + tg2;
                __half h0,l0,h1,l1;
                split_h(acc[mi][ni][0], h0, l0);
                split_h(acc[mi][ni][1], h1, l1);
                *(__half2*)&Dbh[(size_t)row*dStride + col] = __halves2half2(h0, h1);
                *(__half2*)&Dbl[(size_t)row*dStride + col] = __halves2half2(l0, l1);
                split_h(acc[mi][ni][2], h0, l0);
                split_h(acc[mi][ni][3], h1, l1);
                *(__half2*)&Dbh[(size_t)(row+8)*dStride + col] = __halves2half2(h0, h1);
                *(__half2*)&Dbl[(size_t)(row+8)*dStride + col] = __halves2half2(l0, l1);
            }
    } else {
        __half* Dbh = Dh + (size_t)b*dBatch;
#pragma unroll
        for (int mi = 0; mi < 4; mi++)
#pragma unroll
            for (int ni = 0; ni < 4; ni++) {
                int row = M0 + wm*64 + mi*16 + g;
                int col = N0 + wn*32 + ni*8 + tg2;
                *(__half2*)&Dbh[(size_t)row*dStride + col] =
                    __halves2half2(__float2half_rn(acc[mi][ni][0]), __float2half_rn(acc[mi][ni][1]));
                *(__half2*)&Dbh[(size_t)(row+8)*dStride + col] =
                    __halves2half2(__float2half_rn(acc[mi][ni][2]), __float2half_rn(acc[mi][ni][3]));
            }
    }
#undef AHH
#undef ALL_
#undef BHH
#undef BLL
}

// =========================================================================
// merged weight split + stat-buffer zeroing
// =========================================================================
__global__ __launch_bounds__(256) void wsplit_all(
    const float* __restrict__ Wk, const float* __restrict__ Wq,
    const float* __restrict__ Wv, const float* __restrict__ W2)
{
    const int sel = blockIdx.y;
    const float* W = sel == 0 ? Wk : sel == 1 ? Wq : sel == 2 ? Wv : W2;
    __half* h = sel == 0 ? g_wkqh : sel == 1 ? (g_wkqh + CC*CC)
              : sel == 2 ? g_wvh : g_w2h;
    __half* l = sel == 0 ? g_wkql : sel == 1 ? (g_wkql + CC*CC)
              : sel == 2 ? g_wvl : g_w2l;
    int i = blockIdx.x * 256 + threadIdx.x;
    split_h(W[i], h[i], l[i]);
    int z = (blockIdx.y * gridDim.x + blockIdx.x) * 256 + threadIdx.x;
    if (z < NTILES*CC) { (&g_p1[0][0])[z] = 0.f; (&g_p2[0][0])[z] = 0.f; }
}

// =========================================================================
// x transpose + split: x [b][c][n] fp32 -> xT hi/lo [b][n][c]
// =========================================================================
__global__ __launch_bounds__(256) void xsplit_kernel(const float* __restrict__ x)
{
    __shared__ float Tm[32][33];
    const int b = blockIdx.z;
    const float* src = x + (size_t)b*CC*NN;
    __half* dh = g_xth + (size_t)b*NN*CC;
    __half* dl = g_xtl + (size_t)b*NN*CC;
    const int n0 = blockIdx.x * 32, c0 = blockIdx.y * 32;
    const int tx = threadIdx.x & 31, ty = threadIdx.x >> 5;

#pragma unroll
    for (int j = 0; j < 4; j++)
        Tm[ty + j*8][tx] = src[(size_t)(c0 + ty + j*8)*NN + n0 + tx];
    __syncthreads();
#pragma unroll
    for (int j = 0; j < 4; j++) {
        float v = Tm[tx][ty + j*8];
        int n = n0 + ty + j*8;
        __half h, l;
        split_h(v, h, l);
        dh[(size_t)n*CC + c0 + tx] = h;
        dl[(size_t)n*CC + c0 + tx] = l;
    }
}

// =========================================================================
// softmax finalize: per row combine tile (max, expsum) -> scale per tile
// =========================================================================
__global__ __launch_bounds__(256) void smax_fin()
{
    int row = blockIdx.x * 256 + threadIdx.x;     // 0 .. BB*NN-1
    const float* mt = g_mt + (size_t)row*NTILES;
    const float* st = g_st + (size_t)row*NTILES;
    float* sc = g_scale + (size_t)row*NTILES;
    float m = mt[0];
#pragma unroll
    for (int i = 1; i < NTILES; i++) m = fmaxf(m, mt[i]);
    float e[NTILES];
    float tot = 0.f;
#pragma unroll
    for (int i = 0; i < NTILES; i++) { e[i] = __expf(mt[i] - m); tot += st[i]*e[i]; }
    float inv = 1.0f / tot;
#pragma unroll
    for (int i = 0; i < NTILES; i++) sc[i] = e[i]*inv;
}

// =========================================================================
// BN finalize from W2-epilogue partials
// =========================================================================
__global__ __launch_bounds__(256) void bnstats_fin()
{
    const int o = threadIdx.x;
    float S1 = 0.f, S2 = 0.f;
#pragma unroll
    for (int s = 0; s < NTILES; s++) { S1 += g_p1[s][o]; S2 += g_p2[s][o]; }
    const float invM = 1.0f / (float)(BB*NN);
    float mean = S1 * invM;
    float var  = S2 * invM - mean*mean;
    g_mean[o] = mean;
    g_rstd[o] = rsqrtf(var + 1e-5f);
}

// =========================================================================
// normalize + affine + transpose: y [b][n][o] -> out [b][o][n]
// =========================================================================
__global__ __launch_bounds__(256) void bnorm_kernel(
    const float* __restrict__ gamma, const float* __restrict__ beta,
    float* __restrict__ out)
{
    __shared__ float Tm[32][33];
    const int b = blockIdx.z;
    const int n0 = blockIdx.x * 32, o0 = blockIdx.y * 32;
    const int tx = threadIdx.x & 31, ty = threadIdx.x >> 5;
    const float* yb = g_y + (size_t)b*NN*CC;
#pragma unroll
    for (int j = 0; j < 4; j++)
        Tm[ty + j*8][tx] = yb[(size_t)(n0 + ty + j*8)*CC + o0 + tx];
    __syncthreads();
#pragma unroll
    for (int j = 0; j < 4; j++) {
        int o = o0 + ty + j*8;
        float sc = g_rstd[o] * gamma[o];
        float mb = g_mean[o];
        out[((size_t)b*CC + o)*NN + n0 + tx] = (Tm[tx][ty + j*8] - mb) * sc + beta[o];
    }
}

// =========================================================================
extern "C" void kernel_launch(void* const* d_in, const int* in_sizes, int n_in,
                              void* d_out, int out_size)
{
    (void)in_sizes; (void)n_in; (void)out_size;
    const float* x     = (const float*)d_in[0];
    const float* Wk    = (const float*)d_in[1];
    const float* Wq    = (const float*)d_in[2];
    const float* Wv    = (const float*)d_in[3];
    const float* W2    = (const float*)d_in[4];
    const float* b2    = (const float*)d_in[5];
    const float* gamma = (const float*)d_in[6];
    const float* beta  = (const float*)d_in[7];
    float* out = (float*)d_out;

    float *py;
    __half *pxth,*pxtl,*pkqth,*pkqtl,*pv,*pat,*pp;
    __half *pwkqh,*pwkql,*pwvh,*pwvl,*pw2h,*pw2l;
    cudaGetSymbolAddress((void**)&py,    g_y);
    cudaGetSymbolAddress((void**)&pxth,  g_xth);  cudaGetSymbolAddress((void**)&pxtl,  g_xtl);
    cudaGetSymbolAddress((void**)&pkqth, g_kqth); cudaGetSymbolAddress((void**)&pkqtl, g_kqtl);
    cudaGetSymbolAddress((void**)&pv,    g_v);
    cudaGetSymbolAddress((void**)&pat,   g_at);   cudaGetSymbolAddress((void**)&pp,    g_p);
    cudaGetSymbolAddress((void**)&pwkqh, g_wkqh); cudaGetSymbolAddress((void**)&pwkql, g_wkql);
    cudaGetSymbolAddress((void**)&pwvh,  g_wvh);  cudaGetSymbolAddress((void**)&pwvl,  g_wvl);
    cudaGetSymbolAddress((void**)&pw2h,  g_w2h);  cudaGetSymbolAddress((void**)&pw2l,  g_w2l);

    const int SM7 = 2 * (4*128*40) * 2;  // 81920   (TERMS=7, 2 stages)
    const int SM5 = 3 * (3*128*40) * 2;  // 92160   (TERMS=5, 3 stages)
    const int SM3 = 3 * (3*128*40) * 2;  // 92160   (TERMS=3, 3 stages)
    const int SM1 = 4 * (2*128*40) * 2;  // 81920   (TERMS=1, 4 stages)
    cudaFuncSetAttribute(mma_split_gemm<7,2,false,false,false>, cudaFuncAttributeMaxDynamicSharedMemorySize, SM7);
    cudaFuncSetAttribute(mma_split_gemm<5,3,false,false,false>, cudaFuncAttributeMaxDynamicSharedMemorySize, SM5);
    cudaFuncSetAttribute(mma_split_gemm<7,2,false,true,false>,  cudaFuncAttributeMaxDynamicSharedMemorySize, SM7);
    cudaFuncSetAttribute(mma_split_gemm<3,3,true,false,false>,  cudaFuncAttributeMaxDynamicSharedMemorySize, SM3);
    cudaFuncSetAttribute(mma_split_gemm<1,4,false,false,true>,  cudaFuncAttributeMaxDynamicSharedMemorySize, SM1);

    dim3 blk(256);

    wsplit_all<<<dim3(CC*CC/256, 4), blk>>>(Wk, Wq, Wv, W2);

    xsplit_kernel<<<dim3(NN/32, CC/32, BB), blk>>>(x);

    // kqT[b][n][o] = sum_c xT[n][c] * Wkq[o][c]  (3 terms, split out)
    mma_split_gemm<7,2,false,false,false><<<dim3(512/128, NN/128, BB), blk, SM7>>>(
        pxth, pxtl, (size_t)NN*CC, CC,  pwkqh, pwkql, 0, CC,
        nullptr, pkqth, pkqtl, nullptr, (size_t)NN*512, 512, CC);

    // v[b][c][m] = sum_c' Wv[c][c'] * xT[m][c']  (2 terms; single fp16 out)
    mma_split_gemm<5,3,false,false,false><<<dim3(NN/128, CC/128, BB), blk, SM5>>>(
        pwvh, pwvl, 0, CC,  pxth, pxtl, (size_t)NN*CC, CC,
        nullptr, pv, nullptr, nullptr, (size_t)CC*NN, NN, CC);

    // scores + softmax-prep: e = exp(s - m_tile) fp16 into g_p, stats to g_mt/g_st
    mma_split_gemm<7,2,false,true,false><<<dim3(NN/128, NN/128, BB), blk, SM7>>>(
        pkqth, pkqtl, (size_t)NN*512, 512,
        pkqth + CC, pkqtl + CC, (size_t)NN*512, 512,
        nullptr, pp, nullptr, nullptr, (size_t)NN*NN, NN, CC);

    smax_fin<<<BB*NN/256, blk>>>();

    // attnT[b][n][c] = sum_m (e[n][m]*scale[n][m/128]) * v[c][m]
    // scale folded into A fragments (PVSCALE) — no rescale pass.
    mma_split_gemm<1,4,false,false,true><<<dim3(CC/128, NN/128, BB), blk, SM1>>>(
        pp, nullptr, (size_t)NN*NN, NN,  pv, nullptr, (size_t)CC*NN, NN,
        nullptr, pat, nullptr, nullptr, (size_t)NN*CC, CC, NN);

    // y[b][n][o] = sum_c attnT[n][c]*W2[o][c] + b2[o]  (2 terms; fp32 + BN stats)
    mma_split_gemm<3,3,true,false,false><<<dim3(CC/128, NN/128, BB), blk, SM3>>>(
        pat, nullptr, (size_t)NN*CC, CC,  pw2h, pw2l, 0, CC,
        py, nullptr, nullptr, b2, (size_t)NN*CC, CC, CC);

    bnstats_fin<<<1, CC>>>();

    bnorm_kernel<<<dim3(NN/32, CC/32, BB), blk>>>(gamma, beta, out);
}

// round 16
// speedup vs baseline: 1.0268x; 1.0001x over previous
#include <cuda_runtime.h>
#include <cuda_fp16.h>
#include <cstddef>
#include <cstdint>

#define BB 8
#define CC 256
#define NN 2304            // 48*48
#define NTILES 18          // NN/128

// ---------------- scratch (static device memory: allowed) ----------------
__device__ float g_mean[CC];
__device__ float g_rstd[CC];
__device__ float g_p1[NTILES][CC];   // BN partials (W2 epilogue, per N-slab)
__device__ float g_p2[NTILES][CC];
__device__ __align__(16) float g_mt[(size_t)BB*NN*NTILES];    // per-row tile max
__device__ __align__(16) float g_st[(size_t)BB*NN*NTILES];    // per-row tile expsum
__device__ __align__(16) float g_scale[(size_t)BB*NN*NTILES]; // final row-tile scales

// fp16 operands (hi/lo split where needed)
__device__ __align__(16) __half g_xth[(size_t)BB*NN*CC],  g_xtl[(size_t)BB*NN*CC];   // xT [b][n][c]
__device__ __align__(16) __half g_kqth[(size_t)BB*NN*512], g_kqtl[(size_t)BB*NN*512]; // [b][n][k|q]
__device__ __align__(16) __half g_v  [(size_t)BB*CC*NN];                              // v single fp16
__device__ __align__(16) __half g_at [(size_t)BB*NN*CC];                              // attnT single fp16
__device__ __align__(16) __half g_p  [(size_t)BB*NN*NN];                              // e (unscaled exp)
__device__ __align__(16) __half g_yt [(size_t)BB*CC*NN];                              // yT fp16 [b][o][n]
__device__ __align__(16) __half g_wkqh[2*CC*CC], g_wkql[2*CC*CC];  // [Wk;Wq]
__device__ __align__(16) __half g_wvh[CC*CC], g_wvl[CC*CC];
__device__ __align__(16) __half g_w2h[CC*CC], g_w2l[CC*CC];

// ---------------- helpers ----------------
__device__ __forceinline__ void split_h(float f, __half& h, __half& l) {
    h = __float2half_rn(f);
    l = __float2half_rn(f - __half2float(h));
}

__device__ __forceinline__ void ldsm4(uint32_t& r0, uint32_t& r1, uint32_t& r2, uint32_t& r3,
                                      const void* p) {
    uint32_t a = (uint32_t)__cvta_generic_to_shared(p);
    asm volatile("ldmatrix.sync.aligned.m8n8.x4.shared.b16 {%0,%1,%2,%3}, [%4];\n"
                 : "=r"(r0), "=r"(r1), "=r"(r2), "=r"(r3) : "r"(a));
}

__device__ __forceinline__ void mma16816(float* c, const uint32_t* a, const uint32_t* b) {
    asm volatile("mma.sync.aligned.m16n8k16.row.col.f32.f16.f16.f32 "
                 "{%0,%1,%2,%3}, {%4,%5,%6,%7}, {%8,%9}, {%0,%1,%2,%3};\n"
                 : "+f"(c[0]), "+f"(c[1]), "+f"(c[2]), "+f"(c[3])
                 : "r"(a[0]), "r"(a[1]), "r"(a[2]), "r"(a[3]), "r"(b[0]), "r"(b[1]));
}

__device__ __forceinline__ void cpasync16(void* s, const void* g) {
    uint32_t a = (uint32_t)__cvta_generic_to_shared(s);
    asm volatile("cp.async.cg.shared.global [%0], [%1], 16;\n" :: "r"(a), "l"(g));
}
__device__ __forceinline__ void cp_commit() { asm volatile("cp.async.commit_group;\n" ::); }

// =========================================================================
// split-fp16 tensor-core GEMM: D[b][M0+r][N0+c] = sum_k A[r][k]*B[c][k]
// TERMS bitmask: 1 = Ah*Bh (always), 2 = Ah*Bl, 4 = Al*Bh.
// Block tile 128x128, 256 threads (2x4 warps, warp tile 64x32), K-chunk 32,
// NSTAGES-deep cp.async pipeline, 2 CTAs/SM.
// SMAX   : softmax-prep epilogue (writes e=exp(s-m_tile) fp16 + tile stats).
// PVSCALE: multiply A fragments by g_scale[row][k0/128] (softmax rescale fold).
// STATS  : yT-mode epilogue — fp16 output, bias per ROW, fused per-row BN
//          partial sums (atomics into g_p1/g_p2[blockIdx.x][row]).
// =========================================================================
template<int TERMS, int NSTAGES, bool STATS, bool SMAX, bool PVSCALE>
__global__ __launch_bounds__(256, 2) void mma_split_gemm(
    const __half* __restrict__ Ah, const __half* __restrict__ Al,
    size_t aBatch, int aStride,
    const __half* __restrict__ Bh, const __half* __restrict__ Bl,
    size_t bBatch, int bStride,
    float* __restrict__ Df,
    __half* __restrict__ Dh, __half* __restrict__ Dl,
    const float* __restrict__ bias,
    size_t dBatch, int dStride, int Ktot)
{
    constexpr int ABUFS = (TERMS & 4) ? 2 : 1;
    constexpr int BBUFS = (TERMS & 2) ? 2 : 1;
    constexpr int ASZ = 128 * 40;
    constexpr int BSZ = 128 * 40;
    constexpr int STG = ABUFS * ASZ + BBUFS * BSZ;

    extern __shared__ __align__(16) __half smem[];
#define AHH(s)  (smem + (s)*STG)
#define ALL_(s) (smem + (s)*STG + ASZ)
#define BHH(s)  (smem + (s)*STG + ABUFS*ASZ)
#define BLL(s)  (smem + (s)*STG + ABUFS*ASZ + BSZ)

    const int b  = blockIdx.z;
    const int M0 = blockIdx.y * 128;
    const int N0 = blockIdx.x * 128;
    const int tid  = threadIdx.x;
    const int lane = tid & 31;
    const int warp = tid >> 5;
    const int wm = warp >> 2;     // 0..1
    const int wn = warp & 3;      // 0..3

    const __half* Abh = Ah + (size_t)b*aBatch + (size_t)M0*aStride;
    const __half* Abl = (TERMS & 4) ? Al + (size_t)b*aBatch + (size_t)M0*aStride : nullptr;
    const __half* Bbh = Bh + (size_t)b*bBatch + (size_t)N0*bStride;
    const __half* Bbl = (TERMS & 2) ? Bl + (size_t)b*bBatch + (size_t)N0*bStride : nullptr;

    float acc[4][4][4];
#pragma unroll
    for (int i = 0; i < 4; i++)
#pragma unroll
        for (int j = 0; j < 4; j++)
#pragma unroll
            for (int r = 0; r < 4; r++) acc[i][j][r] = 0.f;

    const int T = Ktot >> 5;   // K chunks of 32

    auto load_stage = [&](int s, int k0) {
#pragma unroll
        for (int it = 0; it < 2; it++) {
            int e = tid + it*256;
            int row = e >> 2, seg = (e & 3) * 8;
            cpasync16(AHH(s)+row*40+seg, Abh + (size_t)row*aStride + k0 + seg);
            if (TERMS & 4) cpasync16(ALL_(s)+row*40+seg, Abl + (size_t)row*aStride + k0 + seg);
            cpasync16(BHH(s)+row*40+seg, Bbh + (size_t)row*bStride + k0 + seg);
            if (TERMS & 2) cpasync16(BLL(s)+row*40+seg, Bbl + (size_t)row*bStride + k0 + seg);
        }
    };

#pragma unroll
    for (int s = 0; s < NSTAGES-1; s++) { load_stage(s, s*32); cp_commit(); }

    int cur = 0, fill = NSTAGES - 1;
    for (int t = 0; t < T; t++) {
        asm volatile("cp.async.wait_group %0;\n" :: "n"(NSTAGES-2));
        __syncthreads();

        if (t + NSTAGES - 1 < T) load_stage(fill, (t + NSTAGES - 1) * 32);
        cp_commit();

#pragma unroll
        for (int kk = 0; kk < 32; kk += 16) {
            uint32_t Bfh[4][2], Bfl[4][2];
#pragma unroll
            for (int p = 0; p < 2; p++) {
                int r = wn*32 + p*16 + ((lane >> 4) << 3) + (lane & 7);
                int c = kk + (((lane >> 3) & 1) << 3);
                uint32_t r0, r1, r2, r3;
                ldsm4(r0, r1, r2, r3, BHH(cur)+r*40+c);
                Bfh[2*p][0] = r0; Bfh[2*p][1] = r1;
                Bfh[2*p+1][0] = r2; Bfh[2*p+1][1] = r3;
                if (TERMS & 2) {
                    ldsm4(r0, r1, r2, r3, BLL(cur)+r*40+c);
                    Bfl[2*p][0] = r0; Bfl[2*p][1] = r1;
                    Bfl[2*p+1][0] = r2; Bfl[2*p+1][1] = r3;
                }
            }
#pragma unroll
            for (int mi = 0; mi < 4; mi++) {
                int r = wm*64 + mi*16 + (lane & 15);
                int c = kk + ((lane >> 4) << 3);
                uint32_t Ahf[4], Alf[4];
                ldsm4(Ahf[0], Ahf[1], Ahf[2], Ahf[3], AHH(cur)+r*40+c);
                if (TERMS & 4) ldsm4(Alf[0], Alf[1], Alf[2], Alf[3], ALL_(cur)+r*40+c);

                if (PVSCALE) {
                    // ldmatrix.x4 frag: regs {0,2} = row g, regs {1,3} = row g+8.
                    const int tile = t >> 2;            // k0/128
                    const int rowa = M0 + wm*64 + mi*16 + (lane >> 2);
                    float s0f = g_scale[((size_t)b*NN + rowa)*NTILES + tile];
                    float s1f = g_scale[((size_t)b*NN + rowa + 8)*NTILES + tile];
                    __half2 hs0 = __half2half2(__float2half_rn(s0f));
                    __half2 hs1 = __half2half2(__float2half_rn(s1f));
                    __half2* ah = (__half2*)Ahf;
                    ah[0] = __hmul2(ah[0], hs0);
                    ah[1] = __hmul2(ah[1], hs1);
                    ah[2] = __hmul2(ah[2], hs0);
                    ah[3] = __hmul2(ah[3], hs1);
                }

#pragma unroll
                for (int ni = 0; ni < 4; ni++) mma16816(acc[mi][ni], Ahf, Bfh[ni]);
                if (TERMS & 2) {
#pragma unroll
                    for (int ni = 0; ni < 4; ni++) mma16816(acc[mi][ni], Ahf, Bfl[ni]);
                }
                if (TERMS & 4) {
#pragma unroll
                    for (int ni = 0; ni < 4; ni++) mma16816(acc[mi][ni], Alf, Bfh[ni]);
                }
            }
        }
        cur = (cur + 1 == NSTAGES) ? 0 : cur + 1;
        fill = (fill + 1 == NSTAGES) ? 0 : fill + 1;
    }

    const int g = lane >> 2, tg2 = (lane & 3) * 2;

    if (SMAX) {
        // ------- softmax-prep epilogue -------
        float* maxarr = (float*)smem;          // [128][4]
        float* sumarr = (float*)smem + 512;    // [128][4]
        __syncthreads();   // stage buffers retired; smem reusable

#pragma unroll
        for (int mi = 0; mi < 4; mi++) {
            float m0 = -1e30f, m1 = -1e30f;
#pragma unroll
            for (int ni = 0; ni < 4; ni++) {
                m0 = fmaxf(m0, fmaxf(acc[mi][ni][0], acc[mi][ni][1]));
                m1 = fmaxf(m1, fmaxf(acc[mi][ni][2], acc[mi][ni][3]));
            }
            m0 = fmaxf(m0, __shfl_xor_sync(0xffffffffu, m0, 1));
            m0 = fmaxf(m0, __shfl_xor_sync(0xffffffffu, m0, 2));
            m1 = fmaxf(m1, __shfl_xor_sync(0xffffffffu, m1, 1));
            m1 = fmaxf(m1, __shfl_xor_sync(0xffffffffu, m1, 2));
            if ((lane & 3) == 0) {
                int r0 = wm*64 + mi*16 + g;
                maxarr[r0*4 + wn]     = m0;
                maxarr[(r0+8)*4 + wn] = m1;
            }
        }
        __syncthreads();

        __half* Dbh = Dh + (size_t)b*dBatch;
#pragma unroll
        for (int mi = 0; mi < 4; mi++) {
            int r0 = wm*64 + mi*16 + g;
            float mt0 = fmaxf(fmaxf(maxarr[r0*4+0], maxarr[r0*4+1]),
                              fmaxf(maxarr[r0*4+2], maxarr[r0*4+3]));
            float mt1 = fmaxf(fmaxf(maxarr[(r0+8)*4+0], maxarr[(r0+8)*4+1]),
                              fmaxf(maxarr[(r0+8)*4+2], maxarr[(r0+8)*4+3]));
            float s0 = 0.f, s1 = 0.f;
#pragma unroll
            for (int ni = 0; ni < 4; ni++) {
                int row = M0 + r0;
                int col = N0 + wn*32 + ni*8 + tg2;
                float e0 = __expf(acc[mi][ni][0] - mt0);
                float e1 = __expf(acc[mi][ni][1] - mt0);
                float e2 = __expf(acc[mi][ni][2] - mt1);
                float e3 = __expf(acc[mi][ni][3] - mt1);
                s0 += e0 + e1; s1 += e2 + e3;
                *(__half2*)&Dbh[(size_t)row*dStride + col]     = __floats2half2_rn(e0, e1);
                *(__half2*)&Dbh[(size_t)(row+8)*dStride + col] = __floats2half2_rn(e2, e3);
            }
            s0 += __shfl_xor_sync(0xffffffffu, s0, 1);
            s0 += __shfl_xor_sync(0xffffffffu, s0, 2);
            s1 += __shfl_xor_sync(0xffffffffu, s1, 1);
            s1 += __shfl_xor_sync(0xffffffffu, s1, 2);
            if ((lane & 3) == 0) {
                sumarr[r0*4 + wn]     = s0;
                sumarr[(r0+8)*4 + wn] = s1;
            }
        }
        __syncthreads();

        if (wn == 0 && (lane & 3) == 0) {
            const int tile = blockIdx.x;
#pragma unroll
            for (int mi = 0; mi < 4; mi++) {
                int r0 = wm*64 + mi*16 + g;
#pragma unroll
                for (int h = 0; h < 2; h++) {
                    int r = r0 + h*8;
                    float mm = fmaxf(fmaxf(maxarr[r*4+0], maxarr[r*4+1]),
                                     fmaxf(maxarr[r*4+2], maxarr[r*4+3]));
                    float tt = sumarr[r*4+0]+sumarr[r*4+1]+sumarr[r*4+2]+sumarr[r*4+3];
                    size_t idx = ((size_t)b*NN + M0 + r)*NTILES + tile;
                    g_mt[idx] = mm;
                    g_st[idx] = tt;
                }
            }
        }
    } else if (STATS) {
        // ------- yT-mode: fp16 out, bias per ROW, fused per-row BN stats -------
        __half* Dbh = Dh + (size_t)b*dBatch;
        float s1v[4][2], s2v[4][2];
#pragma unroll
        for (int mi = 0; mi < 4; mi++) { s1v[mi][0]=s1v[mi][1]=s2v[mi][0]=s2v[mi][1]=0.f; }
#pragma unroll
        for (int mi = 0; mi < 4; mi++) {
            int row = M0 + wm*64 + mi*16 + g;
            float bA = bias[row];
            float bB = bias[row + 8];
#pragma unroll
            for (int ni = 0; ni < 4; ni++) {
                int col = N0 + wn*32 + ni*8 + tg2;
                float v0 = acc[mi][ni][0] + bA, v1 = acc[mi][ni][1] + bA;
                float v2 = acc[mi][ni][2] + bB, v3 = acc[mi][ni][3] + bB;
                *(__half2*)&Dbh[(size_t)row*dStride + col]     = __floats2half2_rn(v0, v1);
                *(__half2*)&Dbh[(size_t)(row+8)*dStride + col] = __floats2half2_rn(v2, v3);
                s1v[mi][0] += v0 + v1;          s1v[mi][1] += v2 + v3;
                s2v[mi][0] += v0*v0 + v1*v1;    s2v[mi][1] += v2*v2 + v3*v3;
            }
        }
        // reduce over quad (cols) and atomically add per row into slab = blockIdx.x
#pragma unroll
        for (int mi = 0; mi < 4; mi++)
#pragma unroll
            for (int h = 0; h < 2; h++) {
                s1v[mi][h] += __shfl_xor_sync(0xffffffffu, s1v[mi][h], 1);
                s1v[mi][h] += __shfl_xor_sync(0xffffffffu, s1v[mi][h], 2);
                s2v[mi][h] += __shfl_xor_sync(0xffffffffu, s2v[mi][h], 1);
                s2v[mi][h] += __shfl_xor_sync(0xffffffffu, s2v[mi][h], 2);
            }
        if ((lane & 3) == 0) {
            const int slab = blockIdx.x;
#pragma unroll
            for (int mi = 0; mi < 4; mi++) {
                int row = M0 + wm*64 + mi*16 + g;
                atomicAdd(&g_p1[slab][row],     s1v[mi][0]);
                atomicAdd(&g_p2[slab][row],     s2v[mi][0]);
                atomicAdd(&g_p1[slab][row + 8], s1v[mi][1]);
                atomicAdd(&g_p2[slab][row + 8], s2v[mi][1]);
            }
        }
    } else if (Df) {
        float* Db = Df + (size_t)b*dBatch;
#pragma unroll
        for (int mi = 0; mi < 4; mi++)
#pragma unroll
            for (int ni = 0; ni < 4; ni++) {
                int row = M0 + wm*64 + mi*16 + g;
                int col = N0 + wn*32 + ni*8 + tg2;
                float b0 = bias ? bias[col] : 0.f;
                float b1 = bias ? bias[col+1] : 0.f;
                *(float2*)&Db[(size_t)row*dStride + col] =
                    make_float2(acc[mi][ni][0]+b0, acc[mi][ni][1]+b1);
                *(float2*)&Db[(size_t)(row+8)*dStride + col] =
                    make_float2(acc[mi][ni][2]+b0, acc[mi][ni][3]+b1);
            }
    } else if (Dl) {
        __half* Dbh = Dh + (size_t)b*dBatch;
        __half* Dbl = Dl + (size_t)b*dBatch;
#pragma unroll
        for (int mi = 0; mi < 4; mi++)
#pragma unroll
            for (int ni = 0; ni < 4; ni++) {
                int row = M0 + wm*64 + mi*16 + g;
                int col = N0 + wn*32 + ni*8 + tg2;
                __half h0,l0,h1,l1;
                split_h(acc[mi][ni][0], h0, l0);
                split_h(acc[mi][ni][1], h1, l1);
                *(__half2*)&Dbh[(size_t)row*dStride + col] = __halves2half2(h0, h1);
                *(__half2*)&Dbl[(size_t)row*dStride + col] = __halves2half2(l0, l1);
                split_h(acc[mi][ni][2], h0, l0);
                split_h(acc[mi][ni][3], h1, l1);
                *(__half2*)&Dbh[(size_t)(row+8)*dStride + col] = __halves2half2(h0, h1);
                *(__half2*)&Dbl[(size_t)(row+8)*dStride + col] = __halves2half2(l0, l1);
            }
    } else {
        __half* Dbh = Dh + (size_t)b*dBatch;
#pragma unroll
        for (int mi = 0; mi < 4; mi++)
#pragma unroll
            for (int ni = 0; ni < 4; ni++) {
                int row = M0 + wm*64 + mi*16 + g;
                int col = N0 + wn*32 + ni*8 + tg2;
                *(__half2*)&Dbh[(size_t)row*dStride + col] =
                    __halves2half2(__float2half_rn(acc[mi][ni][0]), __float2half_rn(acc[mi][ni][1]));
                *(__half2*)&Dbh[(size_t)(row+8)*dStride + col] =
                    __halves2half2(__float2half_rn(acc[mi][ni][2]), __float2half_rn(acc[mi][ni][3]));
            }
    }
#undef AHH
#undef ALL_
#undef BHH
#undef BLL
}

// =========================================================================
// merged weight split + stat-buffer zeroing
// =========================================================================
__global__ __launch_bounds__(256) void wsplit_all(
    const float* __restrict__ Wk, const float* __restrict__ Wq,
    const float* __restrict__ Wv, const float* __restrict__ W2)
{
    const int sel = blockIdx.y;
    const float* W = sel == 0 ? Wk : sel == 1 ? Wq : sel == 2 ? Wv : W2;
    __half* h = sel == 0 ? g_wkqh : sel == 1 ? (g_wkqh + CC*CC)
              : sel == 2 ? g_wvh : g_w2h;
    __half* l = sel == 0 ? g_wkql : sel == 1 ? (g_wkql + CC*CC)
              : sel == 2 ? g_wvl : g_w2l;
    int i = blockIdx.x * 256 + threadIdx.x;
    split_h(W[i], h[i], l[i]);
    int z = (blockIdx.y * gridDim.x + blockIdx.x) * 256 + threadIdx.x;
    if (z < NTILES*CC) { (&g_p1[0][0])[z] = 0.f; (&g_p2[0][0])[z] = 0.f; }
}

// =========================================================================
// x transpose + split: x [b][c][n] fp32 -> xT hi/lo [b][n][c]
// =========================================================================
__global__ __launch_bounds__(256) void xsplit_kernel(const float* __restrict__ x)
{
    __shared__ float Tm[32][33];
    const int b = blockIdx.z;
    const float* src = x + (size_t)b*CC*NN;
    __half* dh = g_xth + (size_t)b*NN*CC;
    __half* dl = g_xtl + (size_t)b*NN*CC;
    const int n0 = blockIdx.x * 32, c0 = blockIdx.y * 32;
    const int tx = threadIdx.x & 31, ty = threadIdx.x >> 5;

#pragma unroll
    for (int j = 0; j < 4; j++)
        Tm[ty + j*8][tx] = src[(size_t)(c0 + ty + j*8)*NN + n0 + tx];
    __syncthreads();
#pragma unroll
    for (int j = 0; j < 4; j++) {
        float v = Tm[tx][ty + j*8];
        int n = n0 + ty + j*8;
        __half h, l;
        split_h(v, h, l);
        dh[(size_t)n*CC + c0 + tx] = h;
        dl[(size_t)n*CC + c0 + tx] = l;
    }
}

// =========================================================================
// softmax finalize: per row combine tile (max, expsum) -> scale per tile
// =========================================================================
__global__ __launch_bounds__(256) void smax_fin()
{
    int row = blockIdx.x * 256 + threadIdx.x;     // 0 .. BB*NN-1
    const float* mt = g_mt + (size_t)row*NTILES;
    const float* st = g_st + (size_t)row*NTILES;
    float* sc = g_scale + (size_t)row*NTILES;
    float m = mt[0];
#pragma unroll
    for (int i = 1; i < NTILES; i++) m = fmaxf(m, mt[i]);
    float e[NTILES];
    float tot = 0.f;
#pragma unroll
    for (int i = 0; i < NTILES; i++) { e[i] = __expf(mt[i] - m); tot += st[i]*e[i]; }
    float inv = 1.0f / tot;
#pragma unroll
    for (int i = 0; i < NTILES; i++) sc[i] = e[i]*inv;
}

// =========================================================================
// BN finalize from W2-epilogue partials
// =========================================================================
__global__ __launch_bounds__(256) void bnstats_fin()
{
    const int o = threadIdx.x;
    float S1 = 0.f, S2 = 0.f;
#pragma unroll
    for (int s = 0; s < NTILES; s++) { S1 += g_p1[s][o]; S2 += g_p2[s][o]; }
    const float invM = 1.0f / (float)(BB*NN);
    float mean = S1 * invM;
    float var  = S2 * invM - mean*mean;
    g_mean[o] = mean;
    g_rstd[o] = rsqrtf(var + 1e-5f);
}

// =========================================================================
// normalize + affine, streaming: out[b][o][n] = (yt[b][o][n]-mean)*rstd*g+b
// grid (1, CC, BB), 288 threads x 8 contiguous n
// =========================================================================
__global__ __launch_bounds__(288) void bnorm_kernel(
    const float* __restrict__ gamma, const float* __restrict__ beta,
    float* __restrict__ out)
{
    const int b = blockIdx.z, o = blockIdx.y;
    const int n = threadIdx.x * 8;
    const __half* ysrc = g_yt + ((size_t)b*CC + o)*NN + n;
    float sc = g_rstd[o] * gamma[o];
    float mb = g_mean[o];
    float bt = beta[o];
    uint4 u = *(const uint4*)ysrc;
    const __half2* hp = (const __half2*)&u;
    float4 o0, o1;
    float2 f;
    f = __half22float2(hp[0]); o0.x = (f.x-mb)*sc+bt; o0.y = (f.y-mb)*sc+bt;
    f = __half22float2(hp[1]); o0.z = (f.x-mb)*sc+bt; o0.w = (f.y-mb)*sc+bt;
    f = __half22float2(hp[2]); o1.x = (f.x-mb)*sc+bt; o1.y = (f.y-mb)*sc+bt;
    f = __half22float2(hp[3]); o1.z = (f.x-mb)*sc+bt; o1.w = (f.y-mb)*sc+bt;
    float* dst = out + ((size_t)b*CC + o)*NN + n;
    *(float4*)dst       = o0;
    *(float4*)(dst + 4) = o1;
}

// =========================================================================
extern "C" void kernel_launch(void* const* d_in, const int* in_sizes, int n_in,
                              void* d_out, int out_size)
{
    (void)in_sizes; (void)n_in; (void)out_size;
    const float* x     = (const float*)d_in[0];
    const float* Wk    = (const float*)d_in[1];
    const float* Wq    = (const float*)d_in[2];
    const float* Wv    = (const float*)d_in[3];
    const float* W2    = (const float*)d_in[4];
    const float* b2    = (const float*)d_in[5];
    const float* gamma = (const float*)d_in[6];
    const float* beta  = (const float*)d_in[7];
    float* out = (float*)d_out;

    __half *pxth,*pxtl,*pkqth,*pkqtl,*pv,*pat,*pp,*pyt;
    __half *pwkqh,*pwkql,*pwvh,*pwvl,*pw2h,*pw2l;
    cudaGetSymbolAddress((void**)&pxth,  g_xth);  cudaGetSymbolAddress((void**)&pxtl,  g_xtl);
    cudaGetSymbolAddress((void**)&pkqth, g_kqth); cudaGetSymbolAddress((void**)&pkqtl, g_kqtl);
    cudaGetSymbolAddress((void**)&pv,    g_v);
    cudaGetSymbolAddress((void**)&pat,   g_at);   cudaGetSymbolAddress((void**)&pp,    g_p);
    cudaGetSymbolAddress((void**)&pyt,   g_yt);
    cudaGetSymbolAddress((void**)&pwkqh, g_wkqh); cudaGetSymbolAddress((void**)&pwkql, g_wkql);
    cudaGetSymbolAddress((void**)&pwvh,  g_wvh);  cudaGetSymbolAddress((void**)&pwvl,  g_wvl);
    cudaGetSymbolAddress((void**)&pw2h,  g_w2h);  cudaGetSymbolAddress((void**)&pw2l,  g_w2l);

    const int SM7 = 2 * (4*128*40) * 2;  // 81920   (TERMS=7, 2 stages)
    const int SM5 = 3 * (3*128*40) * 2;  // 92160   (TERMS=5, 3 stages)
    const int SM1 = 4 * (2*128*40) * 2;  // 81920   (TERMS=1, 4 stages)
    cudaFuncSetAttribute(mma_split_gemm<7,2,false,false,false>, cudaFuncAttributeMaxDynamicSharedMemorySize, SM7);
    cudaFuncSetAttribute(mma_split_gemm<5,3,false,false,false>, cudaFuncAttributeMaxDynamicSharedMemorySize, SM5);
    cudaFuncSetAttribute(mma_split_gemm<7,2,false,true,false>,  cudaFuncAttributeMaxDynamicSharedMemorySize, SM7);
    cudaFuncSetAttribute(mma_split_gemm<5,3,true,false,false>,  cudaFuncAttributeMaxDynamicSharedMemorySize, SM5);
    cudaFuncSetAttribute(mma_split_gemm<1,4,false,false,true>,  cudaFuncAttributeMaxDynamicSharedMemorySize, SM1);

    dim3 blk(256);

    wsplit_all<<<dim3(CC*CC/256, 4), blk>>>(Wk, Wq, Wv, W2);

    xsplit_kernel<<<dim3(NN/32, CC/32, BB), blk>>>(x);

    // kqT[b][n][o] = sum_c xT[n][c] * Wkq[o][c]  (3 terms, split out)
    mma_split_gemm<7,2,false,false,false><<<dim3(512/128, NN/128, BB), blk, SM7>>>(
        pxth, pxtl, (size_t)NN*CC, CC,  pwkqh, pwkql, 0, CC,
        nullptr, pkqth, pkqtl, nullptr, (size_t)NN*512, 512, CC);

    // v[b][c][m] = sum_c' Wv[c][c'] * xT[m][c']  (2 terms; single fp16 out)
    mma_split_gemm<5,3,false,false,false><<<dim3(NN/128, CC/128, BB), blk, SM5>>>(
        pwvh, pwvl, 0, CC,  pxth, pxtl, (size_t)NN*CC, CC,
        nullptr, pv, nullptr, nullptr, (size_t)CC*NN, NN, CC);

    // scores + softmax-prep: e = exp(s - m_tile) fp16 into g_p, stats to g_mt/g_st
    mma_split_gemm<7,2,false,true,false><<<dim3(NN/128, NN/128, BB), blk, SM7>>>(
        pkqth, pkqtl, (size_t)NN*512, 512,
        pkqth + CC, pkqtl + CC, (size_t)NN*512, 512,
        nullptr, pp, nullptr, nullptr, (size_t)NN*NN, NN, CC);

    smax_fin<<<BB*NN/256, blk>>>();

    // attnT[b][n][c] = sum_m (e[n][m]*scale[n][m/128]) * v[c][m]  (PVSCALE fold)
    mma_split_gemm<1,4,false,false,true><<<dim3(CC/128, NN/128, BB), blk, SM1>>>(
        pp, nullptr, (size_t)NN*NN, NN,  pv, nullptr, (size_t)CC*NN, NN,
        nullptr, pat, nullptr, nullptr, (size_t)NN*CC, CC, NN);

    // yT[b][o][n] = sum_c W2[o][c]*attnT[n][c] + b2[o]
    // (2 terms: W2 split; fp16 out + fused per-row BN stats)
    mma_split_gemm<5,3,true,false,false><<<dim3(NN/128, CC/128, BB), blk, SM5>>>(
        pw2h, pw2l, 0, CC,  pat, nullptr, (size_t)NN*CC, CC,
        nullptr, pyt, nullptr, b2, (size_t)CC*NN, NN, CC);

    bnstats_fin<<<1, CC>>>();

    bnorm_kernel<<<dim3(1, CC, BB), 288>>>(gamma, beta, out);
}

// round 17
// speedup vs baseline: 1.0375x; 1.0104x over previous
#include <cuda_runtime.h>
#include <cuda_fp16.h>
#include <cstddef>
#include <cstdint>

#define BB 8
#define CC 256
#define NN 2304            // 48*48
#define NTILES 18          // NN/128

// ---------------- scratch (static device memory: allowed) ----------------
__device__ float g_p1[NTILES][CC];   // BN partials (W2 epilogue, per N-slab)
__device__ float g_p2[NTILES][CC];
__device__ __align__(16) float g_mt[(size_t)BB*NN*NTILES];    // per-row tile max
__device__ __align__(16) float g_st[(size_t)BB*NN*NTILES];    // per-row tile expsum

// fp16 operands (hi/lo split where needed)
__device__ __align__(16) __half g_xth[(size_t)BB*NN*CC],  g_xtl[(size_t)BB*NN*CC];   // xT [b][n][c]
__device__ __align__(16) __half g_kqth[(size_t)BB*NN*512], g_kqtl[(size_t)BB*NN*512]; // [b][n][k|q]
__device__ __align__(16) __half g_v  [(size_t)BB*CC*NN];                              // v single fp16
__device__ __align__(16) __half g_at [(size_t)BB*NN*CC];                              // attnT single fp16
__device__ __align__(16) __half g_p  [(size_t)BB*NN*NN];                              // e (unscaled exp)
__device__ __align__(16) __half g_yt [(size_t)BB*CC*NN];                              // yT fp16 [b][o][n]
__device__ __align__(16) __half g_wkqh[2*CC*CC], g_wkql[2*CC*CC];  // [Wk;Wq]
__device__ __align__(16) __half g_wvh[CC*CC], g_wvl[CC*CC];
__device__ __align__(16) __half g_w2h[CC*CC], g_w2l[CC*CC];

// ---------------- helpers ----------------
__device__ __forceinline__ void split_h(float f, __half& h, __half& l) {
    h = __float2half_rn(f);
    l = __float2half_rn(f - __half2float(h));
}

__device__ __forceinline__ void ldsm4(uint32_t& r0, uint32_t& r1, uint32_t& r2, uint32_t& r3,
                                      const void* p) {
    uint32_t a = (uint32_t)__cvta_generic_to_shared(p);
    asm volatile("ldmatrix.sync.aligned.m8n8.x4.shared.b16 {%0,%1,%2,%3}, [%4];\n"
                 : "=r"(r0), "=r"(r1), "=r"(r2), "=r"(r3) : "r"(a));
}

__device__ __forceinline__ void mma16816(float* c, const uint32_t* a, const uint32_t* b) {
    asm volatile("mma.sync.aligned.m16n8k16.row.col.f32.f16.f16.f32 "
                 "{%0,%1,%2,%3}, {%4,%5,%6,%7}, {%8,%9}, {%0,%1,%2,%3};\n"
                 : "+f"(c[0]), "+f"(c[1]), "+f"(c[2]), "+f"(c[3])
                 : "r"(a[0]), "r"(a[1]), "r"(a[2]), "r"(a[3]), "r"(b[0]), "r"(b[1]));
}

__device__ __forceinline__ void cpasync16(void* s, const void* g) {
    uint32_t a = (uint32_t)__cvta_generic_to_shared(s);
    asm volatile("cp.async.cg.shared.global [%0], [%1], 16;\n" :: "r"(a), "l"(g));
}
__device__ __forceinline__ void cp_commit() { asm volatile("cp.async.commit_group;\n" ::); }

// =========================================================================
// split-fp16 tensor-core GEMM: D[b][M0+r][N0+c] = sum_k A[r][k]*B[c][k]
// TERMS bitmask: 1 = Ah*Bh (always), 2 = Ah*Bl, 4 = Al*Bh.
// Block tile 128x128, 256 threads (2x4 warps, warp tile 64x32), K-chunk 32,
// NSTAGES-deep cp.async pipeline, 2 CTAs/SM.
// SMAX   : softmax-prep epilogue (writes e=exp(s-m_tile) fp16 + tile stats).
// PVSCALE: softmax scales computed in PROLOGUE from g_mt/g_st into smem;
//          A fragments multiplied by scale[row][k0/128] from LDS.
// STATS  : yT-mode epilogue — fp16 output, bias per ROW, fused per-row BN
//          partial sums (atomics into g_p1/g_p2[blockIdx.x][row]).
// =========================================================================
template<int TERMS, int NSTAGES, bool STATS, bool SMAX, bool PVSCALE>
__global__ __launch_bounds__(256, 2) void mma_split_gemm(
    const __half* __restrict__ Ah, const __half* __restrict__ Al,
    size_t aBatch, int aStride,
    const __half* __restrict__ Bh, const __half* __restrict__ Bl,
    size_t bBatch, int bStride,
    float* __restrict__ Df,
    __half* __restrict__ Dh, __half* __restrict__ Dl,
    const float* __restrict__ bias,
    size_t dBatch, int dStride, int Ktot)
{
    constexpr int ABUFS = (TERMS & 4) ? 2 : 1;
    constexpr int BBUFS = (TERMS & 2) ? 2 : 1;
    constexpr int ASZ = 128 * 40;
    constexpr int BSZ = 128 * 40;
    constexpr int STG = ABUFS * ASZ + BBUFS * BSZ;

    extern __shared__ __align__(16) __half smem[];
#define AHH(s)  (smem + (s)*STG)
#define ALL_(s) (smem + (s)*STG + ASZ)
#define BHH(s)  (smem + (s)*STG + ABUFS*ASZ)
#define BLL(s)  (smem + (s)*STG + ABUFS*ASZ + BSZ)
    // PVSCALE scale table lives after the stage buffers: [128][19] floats
    float* scl = (float*)(smem + NSTAGES*STG);

    const int b  = blockIdx.z;
    const int M0 = blockIdx.y * 128;
    const int N0 = blockIdx.x * 128;
    const int tid  = threadIdx.x;
    const int lane = tid & 31;
    const int warp = tid >> 5;
    const int wm = warp >> 2;     // 0..1
    const int wn = warp & 3;      // 0..3

    const __half* Abh = Ah + (size_t)b*aBatch + (size_t)M0*aStride;
    const __half* Abl = (TERMS & 4) ? Al + (size_t)b*aBatch + (size_t)M0*aStride : nullptr;
    const __half* Bbh = Bh + (size_t)b*bBatch + (size_t)N0*bStride;
    const __half* Bbl = (TERMS & 2) ? Bl + (size_t)b*bBatch + (size_t)N0*bStride : nullptr;

    float acc[4][4][4];
#pragma unroll
    for (int i = 0; i < 4; i++)
#pragma unroll
        for (int j = 0; j < 4; j++)
#pragma unroll
            for (int r = 0; r < 4; r++) acc[i][j][r] = 0.f;

    const int T = Ktot >> 5;   // K chunks of 32

    auto load_stage = [&](int s, int k0) {
#pragma unroll
        for (int it = 0; it < 2; it++) {
            int e = tid + it*256;
            int row = e >> 2, seg = (e & 3) * 8;
            cpasync16(AHH(s)+row*40+seg, Abh + (size_t)row*aStride + k0 + seg);
            if (TERMS & 4) cpasync16(ALL_(s)+row*40+seg, Abl + (size_t)row*aStride + k0 + seg);
            cpasync16(BHH(s)+row*40+seg, Bbh + (size_t)row*bStride + k0 + seg);
            if (TERMS & 2) cpasync16(BLL(s)+row*40+seg, Bbl + (size_t)row*bStride + k0 + seg);
        }
    };

    // PVSCALE prologue: per-row softmax scales into smem (smax_fin inlined)
    if (PVSCALE) {
        if (tid < 128) {
            int rowg = M0 + tid;
            const float* mt = g_mt + ((size_t)b*NN + rowg)*NTILES;
            const float* st = g_st + ((size_t)b*NN + rowg)*NTILES;
            float m = mt[0];
#pragma unroll
            for (int i = 1; i < NTILES; i++) m = fmaxf(m, mt[i]);
            float e[NTILES];
            float tot = 0.f;
#pragma unroll
            for (int i = 0; i < NTILES; i++) { e[i] = __expf(mt[i] - m); tot += st[i]*e[i]; }
            float inv = 1.0f / tot;
#pragma unroll
            for (int i = 0; i < NTILES; i++) scl[tid*19 + i] = e[i]*inv;
        }
        __syncthreads();
    }

#pragma unroll
    for (int s = 0; s < NSTAGES-1; s++) { load_stage(s, s*32); cp_commit(); }

    int cur = 0, fill = NSTAGES - 1;
    for (int t = 0; t < T; t++) {
        asm volatile("cp.async.wait_group %0;\n" :: "n"(NSTAGES-2));
        __syncthreads();

        if (t + NSTAGES - 1 < T) load_stage(fill, (t + NSTAGES - 1) * 32);
        cp_commit();

#pragma unroll
        for (int kk = 0; kk < 32; kk += 16) {
            uint32_t Bfh[4][2], Bfl[4][2];
#pragma unroll
            for (int p = 0; p < 2; p++) {
                int r = wn*32 + p*16 + ((lane >> 4) << 3) + (lane & 7);
                int c = kk + (((lane >> 3) & 1) << 3);
                uint32_t r0, r1, r2, r3;
                ldsm4(r0, r1, r2, r3, BHH(cur)+r*40+c);
                Bfh[2*p][0] = r0; Bfh[2*p][1] = r1;
                Bfh[2*p+1][0] = r2; Bfh[2*p+1][1] = r3;
                if (TERMS & 2) {
                    ldsm4(r0, r1, r2, r3, BLL(cur)+r*40+c);
                    Bfl[2*p][0] = r0; Bfl[2*p][1] = r1;
                    Bfl[2*p+1][0] = r2; Bfl[2*p+1][1] = r3;
                }
            }
#pragma unroll
            for (int mi = 0; mi < 4; mi++) {
                int r = wm*64 + mi*16 + (lane & 15);
                int c = kk + ((lane >> 4) << 3);
                uint32_t Ahf[4], Alf[4];
                ldsm4(Ahf[0], Ahf[1], Ahf[2], Ahf[3], AHH(cur)+r*40+c);
                if (TERMS & 4) ldsm4(Alf[0], Alf[1], Alf[2], Alf[3], ALL_(cur)+r*40+c);

                if (PVSCALE) {
                    // scale A frags via LDS: regs {0,2} = row g, {1,3} = row g+8
                    const int tile = t >> 2;            // k0/128
                    const int rl = wm*64 + mi*16 + (lane >> 2);
                    float s0f = scl[rl*19 + tile];
                    float s1f = scl[(rl+8)*19 + tile];
                    __half2 hs0 = __half2half2(__float2half_rn(s0f));
                    __half2 hs1 = __half2half2(__float2half_rn(s1f));
                    __half2* ah = (__half2*)Ahf;
                    ah[0] = __hmul2(ah[0], hs0);
                    ah[1] = __hmul2(ah[1], hs1);
                    ah[2] = __hmul2(ah[2], hs0);
                    ah[3] = __hmul2(ah[3], hs1);
                }

#pragma unroll
                for (int ni = 0; ni < 4; ni++) mma16816(acc[mi][ni], Ahf, Bfh[ni]);
                if (TERMS & 2) {
#pragma unroll
                    for (int ni = 0; ni < 4; ni++) mma16816(acc[mi][ni], Ahf, Bfl[ni]);
                }
                if (TERMS & 4) {
#pragma unroll
                    for (int ni = 0; ni < 4; ni++) mma16816(acc[mi][ni], Alf, Bfh[ni]);
                }
            }
        }
        cur = (cur + 1 == NSTAGES) ? 0 : cur + 1;
        fill = (fill + 1 == NSTAGES) ? 0 : fill + 1;
    }

    const int g = lane >> 2, tg2 = (lane & 3) * 2;

    if (SMAX) {
        // ------- softmax-prep epilogue -------
        float* maxarr = (float*)smem;          // [128][4]
        float* sumarr = (float*)smem + 512;    // [128][4]
        __syncthreads();   // stage buffers retired; smem reusable

#pragma unroll
        for (int mi = 0; mi < 4; mi++) {
            float m0 = -1e30f, m1 = -1e30f;
#pragma unroll
            for (int ni = 0; ni < 4; ni++) {
                m0 = fmaxf(m0, fmaxf(acc[mi][ni][0], acc[mi][ni][1]));
                m1 = fmaxf(m1, fmaxf(acc[mi][ni][2], acc[mi][ni][3]));
            }
            m0 = fmaxf(m0, __shfl_xor_sync(0xffffffffu, m0, 1));
            m0 = fmaxf(m0, __shfl_xor_sync(0xffffffffu, m0, 2));
            m1 = fmaxf(m1, __shfl_xor_sync(0xffffffffu, m1, 1));
            m1 = fmaxf(m1, __shfl_xor_sync(0xffffffffu, m1, 2));
            if ((lane & 3) == 0) {
                int r0 = wm*64 + mi*16 + g;
                maxarr[r0*4 + wn]     = m0;
                maxarr[(r0+8)*4 + wn] = m1;
            }
        }
        __syncthreads();

        __half* Dbh = Dh + (size_t)b*dBatch;
#pragma unroll
        for (int mi = 0; mi < 4; mi++) {
            int r0 = wm*64 + mi*16 + g;
            float mt0 = fmaxf(fmaxf(maxarr[r0*4+0], maxarr[r0*4+1]),
                              fmaxf(maxarr[r0*4+2], maxarr[r0*4+3]));
            float mt1 = fmaxf(fmaxf(maxarr[(r0+8)*4+0], maxarr[(r0+8)*4+1]),
                              fmaxf(maxarr[(r0+8)*4+2], maxarr[(r0+8)*4+3]));
            float s0 = 0.f, s1 = 0.f;
#pragma unroll
            for (int ni = 0; ni < 4; ni++) {
                int row = M0 + r0;
                int col = N0 + wn*32 + ni*8 + tg2;
                float e0 = __expf(acc[mi][ni][0] - mt0);
                float e1 = __expf(acc[mi][ni][1] - mt0);
                float e2 = __expf(acc[mi][ni][2] - mt1);
                float e3 = __expf(acc[mi][ni][3] - mt1);
                s0 += e0 + e1; s1 += e2 + e3;
                *(__half2*)&Dbh[(size_t)row*dStride + col]     = __floats2half2_rn(e0, e1);
                *(__half2*)&Dbh[(size_t)(row+8)*dStride + col] = __floats2half2_rn(e2, e3);
            }
            s0 += __shfl_xor_sync(0xffffffffu, s0, 1);
            s0 += __shfl_xor_sync(0xffffffffu, s0, 2);
            s1 += __shfl_xor_sync(0xffffffffu, s1, 1);
            s1 += __shfl_xor_sync(0xffffffffu, s1, 2);
            if ((lane & 3) == 0) {
                sumarr[r0*4 + wn]     = s0;
                sumarr[(r0+8)*4 + wn] = s1;
            }
        }
        __syncthreads();

        if (wn == 0 && (lane & 3) == 0) {
            const int tile = blockIdx.x;
#pragma unroll
            for (int mi = 0; mi < 4; mi++) {
                int r0 = wm*64 + mi*16 + g;
#pragma unroll
                for (int h = 0; h < 2; h++) {
                    int r = r0 + h*8;
                    float mm = fmaxf(fmaxf(maxarr[r*4+0], maxarr[r*4+1]),
                                     fmaxf(maxarr[r*4+2], maxarr[r*4+3]));
                    float tt = sumarr[r*4+0]+sumarr[r*4+1]+sumarr[r*4+2]+sumarr[r*4+3];
                    size_t idx = ((size_t)b*NN + M0 + r)*NTILES + tile;
                    g_mt[idx] = mm;
                    g_st[idx] = tt;
                }
            }
        }
    } else if (STATS) {
        // ------- yT-mode: fp16 out, bias per ROW, fused per-row BN stats -------
        __half* Dbh = Dh + (size_t)b*dBatch;
        float s1v[4][2], s2v[4][2];
#pragma unroll
        for (int mi = 0; mi < 4; mi++) { s1v[mi][0]=s1v[mi][1]=s2v[mi][0]=s2v[mi][1]=0.f; }
#pragma unroll
        for (int mi = 0; mi < 4; mi++) {
            int row = M0 + wm*64 + mi*16 + g;
            float bA = bias[row];
            float bB = bias[row + 8];
#pragma unroll
            for (int ni = 0; ni < 4; ni++) {
                int col = N0 + wn*32 + ni*8 + tg2;
                float v0 = acc[mi][ni][0] + bA, v1 = acc[mi][ni][1] + bA;
                float v2 = acc[mi][ni][2] + bB, v3 = acc[mi][ni][3] + bB;
                *(__half2*)&Dbh[(size_t)row*dStride + col]     = __floats2half2_rn(v0, v1);
                *(__half2*)&Dbh[(size_t)(row+8)*dStride + col] = __floats2half2_rn(v2, v3);
                s1v[mi][0] += v0 + v1;          s1v[mi][1] += v2 + v3;
                s2v[mi][0] += v0*v0 + v1*v1;    s2v[mi][1] += v2*v2 + v3*v3;
            }
        }
#pragma unroll
        for (int mi = 0; mi < 4; mi++)
#pragma unroll
            for (int h = 0; h < 2; h++) {
                s1v[mi][h] += __shfl_xor_sync(0xffffffffu, s1v[mi][h], 1);
                s1v[mi][h] += __shfl_xor_sync(0xffffffffu, s1v[mi][h], 2);
                s2v[mi][h] += __shfl_xor_sync(0xffffffffu, s2v[mi][h], 1);
                s2v[mi][h] += __shfl_xor_sync(0xffffffffu, s2v[mi][h], 2);
            }
        if ((lane & 3) == 0) {
            const int slab = blockIdx.x;
#pragma unroll
            for (int mi = 0; mi < 4; mi++) {
                int row = M0 + wm*64 + mi*16 + g;
                atomicAdd(&g_p1[slab][row],     s1v[mi][0]);
                atomicAdd(&g_p2[slab][row],     s2v[mi][0]);
                atomicAdd(&g_p1[slab][row + 8], s1v[mi][1]);
                atomicAdd(&g_p2[slab][row + 8], s2v[mi][1]);
            }
        }
    } else if (Df) {
        float* Db = Df + (size_t)b*dBatch;
#pragma unroll
        for (int mi = 0; mi < 4; mi++)
#pragma unroll
            for (int ni = 0; ni < 4; ni++) {
                int row = M0 + wm*64 + mi*16 + g;
                int col = N0 + wn*32 + ni*8 + tg2;
                float b0 = bias ? bias[col] : 0.f;
                float b1 = bias ? bias[col+1] : 0.f;
                *(float2*)&Db[(size_t)row*dStride + col] =
                    make_float2(acc[mi][ni][0]+b0, acc[mi][ni][1]+b1);
                *(float2*)&Db[(size_t)(row+8)*dStride + col] =
                    make_float2(acc[mi][ni][2]+b0, acc[mi][ni][3]+b1);
            }
    } else if (Dl) {
        __half* Dbh = Dh + (size_t)b*dBatch;
        __half* Dbl = Dl + (size_t)b*dBatch;
#pragma unroll
        for (int mi = 0; mi < 4; mi++)
#pragma unroll
            for (int ni = 0; ni < 4; ni++) {
                int row = M0 + wm*64 + mi*16 + g;
                int col = N0 + wn*32 + ni*8 + tg2;
                __half h0,l0,h1,l1;
                split_h(acc[mi][ni][0], h0, l0);
                split_h(acc[mi][ni][1], h1, l1);
                *(__half2*)&Dbh[(size_t)row*dStride + col] = __halves2half2(h0, h1);
                *(__half2*)&Dbl[(size_t)row*dStride + col] = __halves2half2(l0, l1);
                split_h(acc[mi][ni][2], h0, l0);
                split_h(acc[mi][ni][3], h1, l1);
                *(__half2*)&Dbh[(size_t)(row+8)*dStride + col] = __halves2half2(h0, h1);
                *(__half2*)&Dbl[(size_t)(row+8)*dStride + col] = __halves2half2(l0, l1);
            }
    } else {
        __half* Dbh = Dh + (size_t)b*dBatch;
#pragma unroll
        for (int mi = 0; mi < 4; mi++)
#pragma unroll
            for (int ni = 0; ni < 4; ni++) {
                int row = M0 + wm*64 + mi*16 + g;
                int col = N0 + wn*32 + ni*8 + tg2;
                *(__half2*)&Dbh[(size_t)row*dStride + col] =
                    __halves2half2(__float2half_rn(acc[mi][ni][0]), __float2half_rn(acc[mi][ni][1]));
                *(__half2*)&Dbh[(size_t)(row+8)*dStride + col] =
                    __halves2half2(__float2half_rn(acc[mi][ni][2]), __float2half_rn(acc[mi][ni][3]));
            }
    }
#undef AHH
#undef ALL_
#undef BHH
#undef BLL
}

// =========================================================================
// merged weight split + stat-buffer zeroing
// =========================================================================
__global__ __launch_bounds__(256) void wsplit_all(
    const float* __restrict__ Wk, const float* __restrict__ Wq,
    const float* __restrict__ Wv, const float* __restrict__ W2)
{
    const int sel = blockIdx.y;
    const float* W = sel == 0 ? Wk : sel == 1 ? Wq : sel == 2 ? Wv : W2;
    __half* h = sel == 0 ? g_wkqh : sel == 1 ? (g_wkqh + CC*CC)
              : sel == 2 ? g_wvh : g_w2h;
    __half* l = sel == 0 ? g_wkql : sel == 1 ? (g_wkql + CC*CC)
              : sel == 2 ? g_wvl : g_w2l;
    int i = blockIdx.x * 256 + threadIdx.x;
    split_h(W[i], h[i], l[i]);
    int z = (blockIdx.y * gridDim.x + blockIdx.x) * 256 + threadIdx.x;
    if (z < NTILES*CC) { (&g_p1[0][0])[z] = 0.f; (&g_p2[0][0])[z] = 0.f; }
}

// =========================================================================
// x transpose + split: x [b][c][n] fp32 -> xT hi/lo [b][n][c]
// =========================================================================
__global__ __launch_bounds__(256) void xsplit_kernel(const float* __restrict__ x)
{
    __shared__ float Tm[32][33];
    const int b = blockIdx.z;
    const float* src = x + (size_t)b*CC*NN;
    __half* dh = g_xth + (size_t)b*NN*CC;
    __half* dl = g_xtl + (size_t)b*NN*CC;
    const int n0 = blockIdx.x * 32, c0 = blockIdx.y * 32;
    const int tx = threadIdx.x & 31, ty = threadIdx.x >> 5;

#pragma unroll
    for (int j = 0; j < 4; j++)
        Tm[ty + j*8][tx] = src[(size_t)(c0 + ty + j*8)*NN + n0 + tx];
    __syncthreads();
#pragma unroll
    for (int j = 0; j < 4; j++) {
        float v = Tm[tx][ty + j*8];
        int n = n0 + ty + j*8;
        __half h, l;
        split_h(v, h, l);
        dh[(size_t)n*CC + c0 + tx] = h;
        dl[(size_t)n*CC + c0 + tx] = l;
    }
}

// =========================================================================
// normalize + affine, streaming, with BN finalize inlined (broadcast loads)
// grid (1, CC, BB), 288 threads x 8 contiguous n
// =========================================================================
__global__ __launch_bounds__(288) void bnorm_kernel(
    const float* __restrict__ gamma, const float* __restrict__ beta,
    float* __restrict__ out)
{
    const int b = blockIdx.z, o = blockIdx.y;
    float S1 = 0.f, S2 = 0.f;
#pragma unroll
    for (int s = 0; s < NTILES; s++) { S1 += g_p1[s][o]; S2 += g_p2[s][o]; }
    const float invM = 1.0f / (float)(BB*NN);
    float mean = S1 * invM;
    float var  = S2 * invM - mean*mean;
    float rstd = rsqrtf(var + 1e-5f);

    const int n = threadIdx.x * 8;
    const __half* ysrc = g_yt + ((size_t)b*CC + o)*NN + n;
    float sc = rstd * gamma[o];
    float bt = beta[o];
    uint4 u = *(const uint4*)ysrc;
    const __half2* hp = (const __half2*)&u;
    float4 o0, o1;
    float2 f;
    f = __half22float2(hp[0]); o0.x = (f.x-mean)*sc+bt; o0.y = (f.y-mean)*sc+bt;
    f = __half22float2(hp[1]); o0.z = (f.x-mean)*sc+bt; o0.w = (f.y-mean)*sc+bt;
    f = __half22float2(hp[2]); o1.x = (f.x-mean)*sc+bt; o1.y = (f.y-mean)*sc+bt;
    f = __half22float2(hp[3]); o1.z = (f.x-mean)*sc+bt; o1.w = (f.y-mean)*sc+bt;
    float* dst = out + ((size_t)b*CC + o)*NN + n;
    *(float4*)dst       = o0;
    *(float4*)(dst + 4) = o1;
}

// =========================================================================
extern "C" void kernel_launch(void* const* d_in, const int* in_sizes, int n_in,
                              void* d_out, int out_size)
{
    (void)in_sizes; (void)n_in; (void)out_size;
    const float* x     = (const float*)d_in[0];
    const float* Wk    = (const float*)d_in[1];
    const float* Wq    = (const float*)d_in[2];
    const float* Wv    = (const float*)d_in[3];
    const float* W2    = (const float*)d_in[4];
    const float* b2    = (const float*)d_in[5];
    const float* gamma = (const float*)d_in[6];
    const float* beta  = (const float*)d_in[7];
    float* out = (float*)d_out;

    __half *pxth,*pxtl,*pkqth,*pkqtl,*pv,*pat,*pp,*pyt;
    __half *pwkqh,*pwkql,*pwvh,*pwvl,*pw2h,*pw2l;
    cudaGetSymbolAddress((void**)&pxth,  g_xth);  cudaGetSymbolAddress((void**)&pxtl,  g_xtl);
    cudaGetSymbolAddress((void**)&pkqth, g_kqth); cudaGetSymbolAddress((void**)&pkqtl, g_kqtl);
    cudaGetSymbolAddress((void**)&pv,    g_v);
    cudaGetSymbolAddress((void**)&pat,   g_at);   cudaGetSymbolAddress((void**)&pp,    g_p);
    cudaGetSymbolAddress((void**)&pyt,   g_yt);
    cudaGetSymbolAddress((void**)&pwkqh, g_wkqh); cudaGetSymbolAddress((void**)&pwkql, g_wkql);
    cudaGetSymbolAddress((void**)&pwvh,  g_wvh);  cudaGetSymbolAddress((void**)&pwvl,  g_wvl);
    cudaGetSymbolAddress((void**)&pw2h,  g_w2h);  cudaGetSymbolAddress((void**)&pw2l,  g_w2l);

    const int SM7 = 2 * (4*128*40) * 2;              // 81920   (TERMS=7, 2 stages)
    const int SM5 = 3 * (3*128*40) * 2;              // 92160   (TERMS=5, 3 stages)
    const int SM1 = 4 * (2*128*40) * 2 + 128*19*4;   // 81920 + 9728 = 91648 (TERMS=1,4st + scales)
    cudaFuncSetAttribute(mma_split_gemm<7,2,false,false,false>, cudaFuncAttributeMaxDynamicSharedMemorySize, SM7);
    cudaFuncSetAttribute(mma_split_gemm<5,3,false,false,false>, cudaFuncAttributeMaxDynamicSharedMemorySize, SM5);
    cudaFuncSetAttribute(mma_split_gemm<7,2,false,true,false>,  cudaFuncAttributeMaxDynamicSharedMemorySize, SM7);
    cudaFuncSetAttribute(mma_split_gemm<5,3,true,false,false>,  cudaFuncAttributeMaxDynamicSharedMemorySize, SM5);
    cudaFuncSetAttribute(mma_split_gemm<1,4,false,false,true>,  cudaFuncAttributeMaxDynamicSharedMemorySize, SM1);

    dim3 blk(256);

    wsplit_all<<<dim3(CC*CC/256, 4), blk>>>(Wk, Wq, Wv, W2);

    xsplit_kernel<<<dim3(NN/32, CC/32, BB), blk>>>(x);

    // kqT[b][n][o] = sum_c xT[n][c] * Wkq[o][c]  (3 terms, split out)
    mma_split_gemm<7,2,false,false,false><<<dim3(512/128, NN/128, BB), blk, SM7>>>(
        pxth, pxtl, (size_t)NN*CC, CC,  pwkqh, pwkql, 0, CC,
        nullptr, pkqth, pkqtl, nullptr, (size_t)NN*512, 512, CC);

    // v[b][c][m] = sum_c' Wv[c][c'] * xT[m][c']  (2 terms; single fp16 out)
    mma_split_gemm<5,3,false,false,false><<<dim3(NN/128, CC/128, BB), blk, SM5>>>(
        pwvh, pwvl, 0, CC,  pxth, pxtl, (size_t)NN*CC, CC,
        nullptr, pv, nullptr, nullptr, (size_t)CC*NN, NN, CC);

    // scores + softmax-prep: e = exp(s - m_tile) fp16 into g_p, stats to g_mt/g_st
    mma_split_gemm<7,2,false,true,false><<<dim3(NN/128, NN/128, BB), blk, SM7>>>(
        pkqth, pkqtl, (size_t)NN*512, 512,
        pkqth + CC, pkqtl + CC, (size_t)NN*512, 512,
        nullptr, pp, nullptr, nullptr, (size_t)NN*NN, NN, CC);

    // attnT[b][n][c] = sum_m (e[n][m]*scale[n][m/128]) * v[c][m]
    // scales computed in-kernel from g_mt/g_st (smax_fin inlined)
    mma_split_gemm<1,4,false,false,true><<<dim3(CC/128, NN/128, BB), blk, SM1>>>(
        pp, nullptr, (size_t)NN*NN, NN,  pv, nullptr, (size_t)CC*NN, NN,
        nullptr, pat, nullptr, nullptr, (size_t)NN*CC, CC, NN);

    // yT[b][o][n] = sum_c W2[o][c]*attnT[n][c] + b2[o]
    // (2 terms: W2 split; fp16 out + fused per-row BN stats)
    mma_split_gemm<5,3,true,false,false><<<dim3(NN/128, CC/128, BB), blk, SM5>>>(
        pw2h, pw2l, 0, CC,  pat, nullptr, (size_t)NN*CC, CC,
        nullptr, pyt, nullptr, b2, (size_t)CC*NN, NN, CC);

    bnorm_kernel<<<dim3(1, CC, BB), 288>>>(gamma, beta, out);
}